// round 8
// baseline (speedup 1.0000x reference)
#include <cuda_runtime.h>
#include <cuda_bf16.h>
#include <math.h>
#include <stdint.h>

#define N_TOK   4096
#define DIM     1024
#define HEADS   8
#define DHEAD   64
#define DINNER  512
#define QKV_N   1536

// Scratch (allocation-free rule: __device__ globals)
__device__ float g_scale[N_TOK];
__device__ __nv_bfloat16 g_xh[(size_t)N_TOK * DIM],     g_xl[(size_t)N_TOK * DIM];
__device__ __nv_bfloat16 g_wqh[(size_t)DIM * QKV_N],    g_wql[(size_t)DIM * QKV_N];   // [K][N]
__device__ __nv_bfloat16 g_woh[(size_t)DINNER * DIM],   g_wol[(size_t)DINNER * DIM];  // [K][N]
__device__ __nv_bfloat16 g_qkvh[(size_t)N_TOK * QKV_N], g_qkvl[(size_t)N_TOK * QKV_N];
__device__ __nv_bfloat16 g_aoh[(size_t)N_TOK * DINNER], g_aol[(size_t)N_TOK * DINNER];

// ---------------------------------------------------------------------------
// Helpers
// ---------------------------------------------------------------------------
__device__ __forceinline__ void mma16816(float* c,
    uint32_t a0, uint32_t a1, uint32_t a2, uint32_t a3,
    uint32_t b0, uint32_t b1) {
    asm volatile(
        "mma.sync.aligned.m16n8k16.row.col.f32.bf16.bf16.f32 "
        "{%0,%1,%2,%3}, {%4,%5,%6,%7}, {%8,%9}, {%0,%1,%2,%3};"
        : "+f"(c[0]), "+f"(c[1]), "+f"(c[2]), "+f"(c[3])
        : "r"(a0), "r"(a1), "r"(a2), "r"(a3), "r"(b0), "r"(b1));
}
__device__ __forceinline__ void ldsm2t(uint32_t& r0, uint32_t& r1, const void* p) {
    uint32_t a = (uint32_t)__cvta_generic_to_shared(p);
    asm volatile("ldmatrix.sync.aligned.m8n8.x2.trans.shared.b16 {%0,%1}, [%2];"
                 : "=r"(r0), "=r"(r1) : "r"(a));
}
__device__ __forceinline__ void split2(float v0, float v1,
                                       uint32_t& hi, uint32_t& lo) {
    __nv_bfloat16 h0 = __float2bfloat16_rn(v0);
    __nv_bfloat16 h1 = __float2bfloat16_rn(v1);
    __nv_bfloat16 l0 = __float2bfloat16_rn(v0 - __bfloat162float(h0));
    __nv_bfloat16 l1 = __float2bfloat16_rn(v1 - __bfloat162float(h1));
    __nv_bfloat162 hp; hp.x = h0; hp.y = h1;
    __nv_bfloat162 lp; lp.x = l0; lp.y = l1;
    hi = *(uint32_t*)&hp;
    lo = *(uint32_t*)&lp;
}
__device__ __forceinline__ void cp16(uint32_t d, const void* s) {
    asm volatile("cp.async.cg.shared.global [%0], [%1], 16;" :: "r"(d), "l"(s));
}
__device__ __forceinline__ void cpcommit() { asm volatile("cp.async.commit_group;" ::: "memory"); }
__device__ __forceinline__ void cpwait0()  { asm volatile("cp.async.wait_group 0;" ::: "memory"); }
__device__ __forceinline__ void cpwait1()  { asm volatile("cp.async.wait_group 1;" ::: "memory"); }

// ---------------------------------------------------------------------------
// Kernel 1: per-row RMS scale
// ---------------------------------------------------------------------------
__global__ void rms_scale_kernel(const float* __restrict__ x) {
    int row = blockIdx.x;
    const float* xr = x + (size_t)row * DIM;
    float s = 0.f;
    for (int i = threadIdx.x; i < DIM; i += 256) {
        float v = xr[i];
        s += v * v;
    }
    #pragma unroll
    for (int o = 16; o; o >>= 1) s += __shfl_xor_sync(0xffffffffu, s, o);
    __shared__ float ws[8];
    if ((threadIdx.x & 31) == 0) ws[threadIdx.x >> 5] = s;
    __syncthreads();
    if (threadIdx.x == 0) {
        float t = 0.f;
        #pragma unroll
        for (int i = 0; i < 8; i++) t += ws[i];
        g_scale[row] = 32.0f / fmaxf(sqrtf(t), 1e-12f);
    }
}

// ---------------------------------------------------------------------------
// Split kernels: fp32 -> bf16 hi/lo pairs
// ---------------------------------------------------------------------------
__global__ void split_x_kernel(const float4* __restrict__ x,
                               const float* __restrict__ gamma) {
    int i = blockIdx.x * 256 + threadIdx.x;
    float4 v = x[i];
    int row = i >> 8;
    int col = (i & 255) * 4;
    float s = g_scale[row];
    float4 gm = *(const float4*)(gamma + col);
    uint32_t h0, l0, h1, l1;
    split2(v.x * s * gm.x, v.y * s * gm.y, h0, l0);
    split2(v.z * s * gm.z, v.w * s * gm.w, h1, l1);
    *(uint2*)&g_xh[(size_t)4 * i] = make_uint2(h0, h1);
    *(uint2*)&g_xl[(size_t)4 * i] = make_uint2(l0, l1);
}

__global__ void split_w_kernel(const float4* __restrict__ w,
                               __nv_bfloat16* __restrict__ hi,
                               __nv_bfloat16* __restrict__ lo) {
    int i = blockIdx.x * 256 + threadIdx.x;
    float4 v = w[i];
    uint32_t h0, l0, h1, l1;
    split2(v.x, v.y, h0, l0);
    split2(v.z, v.w, h1, l1);
    *(uint2*)&hi[(size_t)4 * i] = make_uint2(h0, h1);
    *(uint2*)&lo[(size_t)4 * i] = make_uint2(l0, l1);
}

// ---------------------------------------------------------------------------
// bf16-split HMMA GEMM: C = (Ah+Al)[M,K] @ (Bh+Bl)[K,N], 3-product emulation.
// 128x128 tile, BK=32, 256 thr = 8 warps (4m x 2n), warp tile 32x64.
// Register-staged prefetch: LDG for stage s+1 in flight during compute of s.
// ---------------------------------------------------------------------------
template <bool SPLIT_OUT, int KTOT>
__global__ __launch_bounds__(256)
void mma_gemm_kernel(const __nv_bfloat16* __restrict__ Ah,
                     const __nv_bfloat16* __restrict__ Al,
                     const __nv_bfloat16* __restrict__ Bh,
                     const __nv_bfloat16* __restrict__ Bl,
                     float* __restrict__ C,
                     __nv_bfloat16* __restrict__ Ch,
                     __nv_bfloat16* __restrict__ Cl, int N) {
    __shared__ __align__(16) __nv_bfloat16 As[2][128][40];
    __shared__ __align__(16) __nv_bfloat16 Bs[2][32][136];
    int tid = threadIdx.x;
    int wid = tid >> 5, lane = tid & 31;
    int g = lane >> 2, t = lane & 3;
    int wm = wid & 3, wn = wid >> 2;
    int m0 = blockIdx.y * 128, n0 = blockIdx.x * 128;

    int ar = tid >> 1, ak = (tid & 1) * 16;
    int br = tid >> 3, bc = (tid & 7) * 16;
    const __nv_bfloat16* Aph = Ah + (size_t)(m0 + ar) * KTOT + ak;
    const __nv_bfloat16* Apl = Al + (size_t)(m0 + ar) * KTOT + ak;
    const __nv_bfloat16* Bph = Bh + (size_t)br * N + n0 + bc;
    const __nv_bfloat16* Bpl = Bl + (size_t)br * N + n0 + bc;

    float c[2][8][4];
    #pragma unroll
    for (int mt = 0; mt < 2; mt++)
        #pragma unroll
        for (int nt = 0; nt < 8; nt++)
            #pragma unroll
            for (int e = 0; e < 4; e++) c[mt][nt][e] = 0.f;

    uint4 rah[2], ral[2], rbh[2], rbl[2];
    rah[0] = *(const uint4*)Aph;       rah[1] = *(const uint4*)(Aph + 8);
    ral[0] = *(const uint4*)Apl;       ral[1] = *(const uint4*)(Apl + 8);
    rbh[0] = *(const uint4*)Bph;       rbh[1] = *(const uint4*)(Bph + 8);
    rbl[0] = *(const uint4*)Bpl;       rbl[1] = *(const uint4*)(Bpl + 8);

    const int S = KTOT / 32;
    for (int s = 0; s < S; s++) {
        *(uint4*)&As[0][ar][ak]     = rah[0];
        *(uint4*)&As[0][ar][ak + 8] = rah[1];
        *(uint4*)&As[1][ar][ak]     = ral[0];
        *(uint4*)&As[1][ar][ak + 8] = ral[1];
        *(uint4*)&Bs[0][br][bc]     = rbh[0];
        *(uint4*)&Bs[0][br][bc + 8] = rbh[1];
        *(uint4*)&Bs[1][br][bc]     = rbl[0];
        *(uint4*)&Bs[1][br][bc + 8] = rbl[1];
        __syncthreads();
        if (s + 1 < S) {
            int ko = (s + 1) * 32;
            rah[0] = *(const uint4*)(Aph + ko);     rah[1] = *(const uint4*)(Aph + ko + 8);
            ral[0] = *(const uint4*)(Apl + ko);     ral[1] = *(const uint4*)(Apl + ko + 8);
            rbh[0] = *(const uint4*)(Bph + (size_t)ko * N);
            rbh[1] = *(const uint4*)(Bph + (size_t)ko * N + 8);
            rbl[0] = *(const uint4*)(Bpl + (size_t)ko * N);
            rbl[1] = *(const uint4*)(Bpl + (size_t)ko * N + 8);
        }
        #pragma unroll
        for (int kk = 0; kk < 32; kk += 16) {
            uint32_t ah[2][4], al[2][4];
            #pragma unroll
            for (int mt = 0; mt < 2; mt++) {
                int r = wm * 32 + mt * 16;
                ah[mt][0] = *(const uint32_t*)&As[0][r + g][kk + 2 * t];
                ah[mt][1] = *(const uint32_t*)&As[0][r + 8 + g][kk + 2 * t];
                ah[mt][2] = *(const uint32_t*)&As[0][r + g][kk + 8 + 2 * t];
                ah[mt][3] = *(const uint32_t*)&As[0][r + 8 + g][kk + 8 + 2 * t];
                al[mt][0] = *(const uint32_t*)&As[1][r + g][kk + 2 * t];
                al[mt][1] = *(const uint32_t*)&As[1][r + 8 + g][kk + 2 * t];
                al[mt][2] = *(const uint32_t*)&As[1][r + g][kk + 8 + 2 * t];
                al[mt][3] = *(const uint32_t*)&As[1][r + 8 + g][kk + 8 + 2 * t];
            }
            #pragma unroll
            for (int nt = 0; nt < 8; nt++) {
                uint32_t bh0, bh1, bl0, bl1;
                ldsm2t(bh0, bh1, &Bs[0][kk + (lane & 15)][wn * 64 + nt * 8]);
                ldsm2t(bl0, bl1, &Bs[1][kk + (lane & 15)][wn * 64 + nt * 8]);
                #pragma unroll
                for (int mt = 0; mt < 2; mt++) {
                    mma16816(c[mt][nt], ah[mt][0], ah[mt][1], ah[mt][2], ah[mt][3], bh0, bh1);
                    mma16816(c[mt][nt], ah[mt][0], ah[mt][1], ah[mt][2], ah[mt][3], bl0, bl1);
                    mma16816(c[mt][nt], al[mt][0], al[mt][1], al[mt][2], al[mt][3], bh0, bh1);
                }
            }
        }
        __syncthreads();
    }
    #pragma unroll
    for (int mt = 0; mt < 2; mt++) {
        #pragma unroll
        for (int nt = 0; nt < 8; nt++) {
            int rowA = m0 + wm * 32 + mt * 16 + g;
            int col = n0 + wn * 64 + nt * 8 + 2 * t;
            if (SPLIT_OUT) {
                uint32_t hi, lo;
                split2(c[mt][nt][0], c[mt][nt][1], hi, lo);
                *(uint32_t*)&Ch[(size_t)rowA * N + col] = hi;
                *(uint32_t*)&Cl[(size_t)rowA * N + col] = lo;
                split2(c[mt][nt][2], c[mt][nt][3], hi, lo);
                *(uint32_t*)&Ch[(size_t)(rowA + 8) * N + col] = hi;
                *(uint32_t*)&Cl[(size_t)(rowA + 8) * N + col] = lo;
            } else {
                *(float2*)&C[(size_t)rowA * N + col] =
                    make_float2(c[mt][nt][0], c[mt][nt][1]);
                *(float2*)&C[(size_t)(rowA + 8) * N + col] =
                    make_float2(c[mt][nt][2], c[mt][nt][3]);
            }
        }
    }
}

// ---------------------------------------------------------------------------
// Flash attention (HMMA bf16-split), 128-row Q tiles, 256 thr = 8 warps.
// K/V tiles (64 keys) double-buffered via cp.async. Q frags in registers.
// Fully-masked warps skip compute. Logits scaled by sqrt(d)=8 post-mma.
// ---------------------------------------------------------------------------
#define ASM_ELE (64 * 72)
#define ATT_SMEM (2 * 4 * ASM_ELE * 2)   // 2 stages x {Kh,Kl,Vh,Vl} x bf16

__global__ __launch_bounds__(256)
void mma_attn_kernel(const __nv_bfloat16* __restrict__ qh,
                     const __nv_bfloat16* __restrict__ ql,
                     __nv_bfloat16* __restrict__ aoh,
                     __nv_bfloat16* __restrict__ aol) {
    extern __shared__ __align__(16) __nv_bfloat16 smb[];
    uint32_t smb_u = (uint32_t)__cvta_generic_to_shared(smb);

    int qt = 31 - blockIdx.x;          // heavy tiles first
    int h = blockIdx.y;
    int tid = threadIdx.x;
    int wid = tid >> 5, lane = tid & 31;
    int g = lane >> 2, t = lane & 3;
    int r0 = wid * 16;
    int gA = qt * 128 + r0 + g;        // warp's first row group
    int ktmax = 2 * qt + 1;

    // Q fragments direct from gmem (loop-invariant)
    uint32_t ahq[4][4], alq[4][4];
    {
        size_t rA = (size_t)gA * QKV_N + h * DHEAD;
        size_t rB = (size_t)(gA + 8) * QKV_N + h * DHEAD;
        #pragma unroll
        for (int d16 = 0; d16 < 4; d16++) {
            int cA = d16 * 16 + 2 * t, cB = d16 * 16 + 8 + 2 * t;
            ahq[d16][0] = *(const uint32_t*)&qh[rA + cA];
            ahq[d16][1] = *(const uint32_t*)&qh[rB + cA];
            ahq[d16][2] = *(const uint32_t*)&qh[rA + cB];
            ahq[d16][3] = *(const uint32_t*)&qh[rB + cB];
            alq[d16][0] = *(const uint32_t*)&ql[rA + cA];
            alq[d16][1] = *(const uint32_t*)&ql[rB + cA];
            alq[d16][2] = *(const uint32_t*)&ql[rA + cB];
            alq[d16][3] = *(const uint32_t*)&ql[rB + cB];
        }
    }

    // stage loader: Kh | Kl | Vh | Vl, each [64][72]
    #define LOAD_KV(kt_, buf_) do {                                            \
        uint32_t sbase = smb_u + (buf_) * (4 * ASM_ELE * 2);                   \
        _Pragma("unroll")                                                      \
        for (int j = 0; j < 2; j++) {                                          \
            int p = tid + j * 256;                                             \
            int rr = p >> 3, c8 = (p & 7) * 8;                                 \
            uint32_t dso = rr * 144 + c8 * 2;                                  \
            size_t base = (size_t)((kt_) * 64 + rr) * QKV_N + h * DHEAD + c8;  \
            cp16(sbase + dso,                    qh + base + DINNER);          \
            cp16(sbase + ASM_ELE * 2 + dso,      ql + base + DINNER);          \
            cp16(sbase + 2 * ASM_ELE * 2 + dso,  qh + base + 2 * DINNER);      \
            cp16(sbase + 3 * ASM_ELE * 2 + dso,  ql + base + 2 * DINNER);      \
        }                                                                      \
        cpcommit();                                                            \
    } while (0)

    float o[8][4];
    #pragma unroll
    for (int nt = 0; nt < 8; nt++)
        #pragma unroll
        for (int e = 0; e < 4; e++) o[nt][e] = 0.f;
    float m[2] = {-1e30f, -1e30f}, l[2] = {0.f, 0.f};

    LOAD_KV(0, 0);

    for (int kt = 0; kt <= ktmax; kt++) {
        __syncthreads();                       // prev compute done -> buffer free
        if (kt + 1 <= ktmax) { LOAD_KV(kt + 1, (kt + 1) & 1); cpwait1(); }
        else                 { cpwait0(); }
        __syncthreads();                       // stage kt visible to all

        if (kt * 64 > qt * 128 + r0 + 15) continue;   // fully masked for this warp

        const __nv_bfloat16* Kh = smb + (kt & 1) * (4 * ASM_ELE);
        const __nv_bfloat16* Kl = Kh + ASM_ELE;
        const __nv_bfloat16* Vh = Kh + 2 * ASM_ELE;
        const __nv_bfloat16* Vl = Kh + 3 * ASM_ELE;

        float sc[8][4];
        #pragma unroll
        for (int nt = 0; nt < 8; nt++)
            #pragma unroll
            for (int e = 0; e < 4; e++) sc[nt][e] = 0.f;

        #pragma unroll
        for (int d16 = 0; d16 < 4; d16++) {
            #pragma unroll
            for (int nt = 0; nt < 8; nt++) {
                uint32_t bh0 = *(const uint32_t*)&Kh[(nt * 8 + g) * 72 + d16 * 16 + 2 * t];
                uint32_t bh1 = *(const uint32_t*)&Kh[(nt * 8 + g) * 72 + d16 * 16 + 8 + 2 * t];
                uint32_t bl0 = *(const uint32_t*)&Kl[(nt * 8 + g) * 72 + d16 * 16 + 2 * t];
                uint32_t bl1 = *(const uint32_t*)&Kl[(nt * 8 + g) * 72 + d16 * 16 + 8 + 2 * t];
                mma16816(sc[nt], ahq[d16][0], ahq[d16][1], ahq[d16][2], ahq[d16][3], bh0, bh1);
                mma16816(sc[nt], ahq[d16][0], ahq[d16][1], ahq[d16][2], ahq[d16][3], bl0, bl1);
                mma16816(sc[nt], alq[d16][0], alq[d16][1], alq[d16][2], alq[d16][3], bh0, bh1);
            }
        }

        #pragma unroll
        for (int nt = 0; nt < 8; nt++)
            #pragma unroll
            for (int e = 0; e < 4; e++) sc[nt][e] *= 8.f;

        // FIX (R7 bug): mask whenever the tile's max column exceeds the warp's
        // MIN row (qt*128 + r0), not its max row. With r0 on a 16 grid and
        // C on a 64 grid, C+63 can land inside (R, R+15] and the old gate
        // skipped masking entirely for warps 3 and 7 of every CTA.
        if (kt * 64 + 63 > qt * 128 + r0) {
            #pragma unroll
            for (int nt = 0; nt < 8; nt++) {
                int gc = kt * 64 + nt * 8 + 2 * t;
                if (gc > gA)         sc[nt][0] = -1e30f;
                if (gc + 1 > gA)     sc[nt][1] = -1e30f;
                if (gc > gA + 8)     sc[nt][2] = -1e30f;
                if (gc + 1 > gA + 8) sc[nt][3] = -1e30f;
            }
        }

        #pragma unroll
        for (int hf = 0; hf < 2; hf++) {
            float mx = -1e30f;
            #pragma unroll
            for (int nt = 0; nt < 8; nt++) {
                mx = fmaxf(mx, sc[nt][2 * hf]);
                mx = fmaxf(mx, sc[nt][2 * hf + 1]);
            }
            mx = fmaxf(mx, __shfl_xor_sync(0xffffffffu, mx, 1));
            mx = fmaxf(mx, __shfl_xor_sync(0xffffffffu, mx, 2));
            float mnew = fmaxf(m[hf], mx);
            float corr = __expf(m[hf] - mnew);
            m[hf] = mnew;
            float sum = 0.f;
            #pragma unroll
            for (int nt = 0; nt < 8; nt++) {
                float p0 = __expf(sc[nt][2 * hf] - mnew);
                float p1 = __expf(sc[nt][2 * hf + 1] - mnew);
                sc[nt][2 * hf] = p0;
                sc[nt][2 * hf + 1] = p1;
                sum += p0 + p1;
            }
            sum += __shfl_xor_sync(0xffffffffu, sum, 1);
            sum += __shfl_xor_sync(0xffffffffu, sum, 2);
            l[hf] = l[hf] * corr + sum;
            #pragma unroll
            for (int nt = 0; nt < 8; nt++) {
                o[nt][2 * hf] *= corr;
                o[nt][2 * hf + 1] *= corr;
            }
        }

        uint32_t phf[4][4], plf[4][4];
        #pragma unroll
        for (int kk = 0; kk < 4; kk++) {
            split2(sc[2 * kk][0], sc[2 * kk][1], phf[kk][0], plf[kk][0]);
            split2(sc[2 * kk][2], sc[2 * kk][3], phf[kk][1], plf[kk][1]);
            split2(sc[2 * kk + 1][0], sc[2 * kk + 1][1], phf[kk][2], plf[kk][2]);
            split2(sc[2 * kk + 1][2], sc[2 * kk + 1][3], phf[kk][3], plf[kk][3]);
        }

        #pragma unroll
        for (int nt = 0; nt < 8; nt++) {
            #pragma unroll
            for (int kk = 0; kk < 4; kk++) {
                uint32_t vh0, vh1, vl0, vl1;
                ldsm2t(vh0, vh1, &Vh[(kk * 16 + (lane & 15)) * 72 + nt * 8]);
                ldsm2t(vl0, vl1, &Vl[(kk * 16 + (lane & 15)) * 72 + nt * 8]);
                mma16816(o[nt], phf[kk][0], phf[kk][1], phf[kk][2], phf[kk][3], vh0, vh1);
                mma16816(o[nt], phf[kk][0], phf[kk][1], phf[kk][2], phf[kk][3], vl0, vl1);
                mma16816(o[nt], plf[kk][0], plf[kk][1], plf[kk][2], plf[kk][3], vh0, vh1);
            }
        }
    }

    float inv0 = 1.f / l[0], inv1 = 1.f / l[1];
    #pragma unroll
    for (int nt = 0; nt < 8; nt++) {
        int col = h * DHEAD + nt * 8 + 2 * t;
        size_t rA = (size_t)gA * DINNER + col;
        size_t rB = (size_t)(gA + 8) * DINNER + col;
        uint32_t hi, lo;
        split2(o[nt][0] * inv0, o[nt][1] * inv0, hi, lo);
        *(uint32_t*)&aoh[rA] = hi;
        *(uint32_t*)&aol[rA] = lo;
        split2(o[nt][2] * inv1, o[nt][3] * inv1, hi, lo);
        *(uint32_t*)&aoh[rB] = hi;
        *(uint32_t*)&aol[rB] = lo;
    }
    #undef LOAD_KV
}

// ---------------------------------------------------------------------------
extern "C" void kernel_launch(void* const* d_in, const int* in_sizes, int n_in,
                              void* d_out, int out_size) {
    const float* x     = (const float*)d_in[0];
    const float* gamma = (const float*)d_in[1];
    const float* w_qkv = (const float*)d_in[2];
    const float* w_out = (const float*)d_in[3];
    float* out = (float*)d_out;

    __nv_bfloat16 *xh, *xl, *wqh, *wql, *woh, *wol, *qkvh, *qkvl, *aoh, *aol;
    cudaGetSymbolAddress((void**)&xh, g_xh);
    cudaGetSymbolAddress((void**)&xl, g_xl);
    cudaGetSymbolAddress((void**)&wqh, g_wqh);
    cudaGetSymbolAddress((void**)&wql, g_wql);
    cudaGetSymbolAddress((void**)&woh, g_woh);
    cudaGetSymbolAddress((void**)&wol, g_wol);
    cudaGetSymbolAddress((void**)&qkvh, g_qkvh);
    cudaGetSymbolAddress((void**)&qkvl, g_qkvl);
    cudaGetSymbolAddress((void**)&aoh, g_aoh);
    cudaGetSymbolAddress((void**)&aol, g_aol);

    cudaFuncSetAttribute(mma_attn_kernel,
                         cudaFuncAttributeMaxDynamicSharedMemorySize, ATT_SMEM);

    rms_scale_kernel<<<N_TOK, 256>>>(x);
    split_x_kernel<<<(N_TOK * DIM / 4) / 256, 256>>>((const float4*)x, gamma);
    split_w_kernel<<<(DIM * QKV_N / 4) / 256, 256>>>((const float4*)w_qkv, wqh, wql);
    split_w_kernel<<<(DINNER * DIM / 4) / 256, 256>>>((const float4*)w_out, woh, wol);

    mma_gemm_kernel<true, 1024><<<dim3(QKV_N / 128, N_TOK / 128), 256>>>(
        xh, xl, wqh, wql, nullptr, qkvh, qkvl, QKV_N);

    mma_attn_kernel<<<dim3(32, 8), 256, ATT_SMEM>>>(qkvh, qkvl, aoh, aol);

    mma_gemm_kernel<false, 512><<<dim3(DIM / 128, N_TOK / 128), 256>>>(
        aoh, aol, woh, wol, out, nullptr, nullptr, DIM);
}

// round 9
// speedup vs baseline: 1.2095x; 1.2095x over previous
#include <cuda_runtime.h>
#include <cuda_bf16.h>
#include <math.h>
#include <stdint.h>

#define N_TOK   4096
#define DIM     1024
#define HEADS   8
#define DHEAD   64
#define DINNER  512
#define QKV_N   1536

// Scratch (allocation-free rule: __device__ globals)
__device__ float g_scale[N_TOK];
__device__ __nv_bfloat16 g_xh[(size_t)N_TOK * DIM],     g_xl[(size_t)N_TOK * DIM];
__device__ __nv_bfloat16 g_wqh[(size_t)DIM * QKV_N],    g_wql[(size_t)DIM * QKV_N];
__device__ __nv_bfloat16 g_woh[(size_t)DINNER * DIM],   g_wol[(size_t)DINNER * DIM];
__device__ __nv_bfloat16 g_qkvh[(size_t)N_TOK * QKV_N], g_qkvl[(size_t)N_TOK * QKV_N];
__device__ __nv_bfloat16 g_aoh[(size_t)N_TOK * DINNER], g_aol[(size_t)N_TOK * DINNER];

// ---------------------------------------------------------------------------
// Helpers
// ---------------------------------------------------------------------------
__device__ __forceinline__ void mma16816(float* c,
    uint32_t a0, uint32_t a1, uint32_t a2, uint32_t a3,
    uint32_t b0, uint32_t b1) {
    asm volatile(
        "mma.sync.aligned.m16n8k16.row.col.f32.bf16.bf16.f32 "
        "{%0,%1,%2,%3}, {%4,%5,%6,%7}, {%8,%9}, {%0,%1,%2,%3};"
        : "+f"(c[0]), "+f"(c[1]), "+f"(c[2]), "+f"(c[3])
        : "r"(a0), "r"(a1), "r"(a2), "r"(a3), "r"(b0), "r"(b1));
}
__device__ __forceinline__ void ldsm2t(uint32_t& r0, uint32_t& r1, const void* p) {
    uint32_t a = (uint32_t)__cvta_generic_to_shared(p);
    asm volatile("ldmatrix.sync.aligned.m8n8.x2.trans.shared.b16 {%0,%1}, [%2];"
                 : "=r"(r0), "=r"(r1) : "r"(a));
}
__device__ __forceinline__ void split2(float v0, float v1,
                                       uint32_t& hi, uint32_t& lo) {
    __nv_bfloat16 h0 = __float2bfloat16_rn(v0);
    __nv_bfloat16 h1 = __float2bfloat16_rn(v1);
    __nv_bfloat16 l0 = __float2bfloat16_rn(v0 - __bfloat162float(h0));
    __nv_bfloat16 l1 = __float2bfloat16_rn(v1 - __bfloat162float(h1));
    __nv_bfloat162 hp; hp.x = h0; hp.y = h1;
    __nv_bfloat162 lp; lp.x = l0; lp.y = l1;
    hi = *(uint32_t*)&hp;
    lo = *(uint32_t*)&lp;
}

// ---------------------------------------------------------------------------
// Kernel 1: per-row RMS scale = sqrt(DIM) / max(||x_row||, 1e-12)
// ---------------------------------------------------------------------------
__global__ void rms_scale_kernel(const float* __restrict__ x) {
    int row = blockIdx.x;
    const float* xr = x + (size_t)row * DIM;
    float s = 0.f;
    for (int i = threadIdx.x; i < DIM; i += 256) {
        float v = xr[i];
        s += v * v;
    }
    #pragma unroll
    for (int o = 16; o; o >>= 1) s += __shfl_xor_sync(0xffffffffu, s, o);
    __shared__ float ws[8];
    if ((threadIdx.x & 31) == 0) ws[threadIdx.x >> 5] = s;
    __syncthreads();
    if (threadIdx.x == 0) {
        float t = 0.f;
        #pragma unroll
        for (int i = 0; i < 8; i++) t += ws[i];
        g_scale[row] = 32.0f / fmaxf(sqrtf(t), 1e-12f);
    }
}

// ---------------------------------------------------------------------------
// Split kernels: fp32 -> bf16 hi/lo pairs
// ---------------------------------------------------------------------------
__global__ void split_x_kernel(const float4* __restrict__ x,
                               const float* __restrict__ gamma) {
    int i = blockIdx.x * 256 + threadIdx.x;
    float4 v = x[i];
    int row = i >> 8;
    int col = (i & 255) * 4;
    float s = g_scale[row];
    float4 gm = *(const float4*)(gamma + col);
    uint32_t h0, l0, h1, l1;
    split2(v.x * s * gm.x, v.y * s * gm.y, h0, l0);
    split2(v.z * s * gm.z, v.w * s * gm.w, h1, l1);
    *(uint2*)&g_xh[(size_t)4 * i] = make_uint2(h0, h1);
    *(uint2*)&g_xl[(size_t)4 * i] = make_uint2(l0, l1);
}

__global__ void split_w_kernel(const float4* __restrict__ w,
                               __nv_bfloat16* __restrict__ hi,
                               __nv_bfloat16* __restrict__ lo) {
    int i = blockIdx.x * 256 + threadIdx.x;
    float4 v = w[i];
    uint32_t h0, l0, h1, l1;
    split2(v.x, v.y, h0, l0);
    split2(v.z, v.w, h1, l1);
    *(uint2*)&hi[(size_t)4 * i] = make_uint2(h0, h1);
    *(uint2*)&lo[(size_t)4 * i] = make_uint2(l0, l1);
}

// ---------------------------------------------------------------------------
// bf16-split HMMA GEMM (R5 version, proven): C = (Ah+Al) @ (Bh+Bl).
// Block tile 128(M) x 64(N), BK=32, 256 thr = 8 warps (4m x 2n),
// warp tile 32x32 = 2 m16-tiles x 4 n8-tiles.
// ---------------------------------------------------------------------------
template <bool SPLIT_OUT>
__global__ __launch_bounds__(256)
void mma_gemm_kernel(const __nv_bfloat16* __restrict__ Ah,
                     const __nv_bfloat16* __restrict__ Al,
                     const __nv_bfloat16* __restrict__ Bh,
                     const __nv_bfloat16* __restrict__ Bl,
                     float* __restrict__ C,
                     __nv_bfloat16* __restrict__ Ch,
                     __nv_bfloat16* __restrict__ Cl,
                     int M, int N, int K) {
    __shared__ __align__(16) __nv_bfloat16 As[2][128][40];
    __shared__ __align__(16) __nv_bfloat16 Bs[2][32][72];
    int tid = threadIdx.x;
    int wid = tid >> 5, lane = tid & 31;
    int g = lane >> 2, t = lane & 3;
    int wm = wid & 3, wn = wid >> 2;
    int m0 = blockIdx.y * 128, n0 = blockIdx.x * 64;

    float c[2][4][4];
    #pragma unroll
    for (int mt = 0; mt < 2; mt++)
        #pragma unroll
        for (int nt = 0; nt < 4; nt++)
            #pragma unroll
            for (int e = 0; e < 4; e++) c[mt][nt][e] = 0.f;

    for (int k0 = 0; k0 < K; k0 += 32) {
        #pragma unroll
        for (int i = 0; i < 2; i++) {
            int p = tid + 256 * i;
            int ar = p >> 2, ak = (p & 3) * 8;
            *(uint4*)&As[0][ar][ak] = *(const uint4*)&Ah[(size_t)(m0 + ar) * K + k0 + ak];
            *(uint4*)&As[1][ar][ak] = *(const uint4*)&Al[(size_t)(m0 + ar) * K + k0 + ak];
        }
        {
            int br = tid >> 3, bn = (tid & 7) * 8;
            *(uint4*)&Bs[0][br][bn] = *(const uint4*)&Bh[(size_t)(k0 + br) * N + n0 + bn];
            *(uint4*)&Bs[1][br][bn] = *(const uint4*)&Bl[(size_t)(k0 + br) * N + n0 + bn];
        }
        __syncthreads();
        #pragma unroll
        for (int kk = 0; kk < 32; kk += 16) {
            uint32_t ah[2][4], al[2][4];
            #pragma unroll
            for (int mt = 0; mt < 2; mt++) {
                int r = wm * 32 + mt * 16;
                ah[mt][0] = *(const uint32_t*)&As[0][r + g][kk + 2 * t];
                ah[mt][1] = *(const uint32_t*)&As[0][r + 8 + g][kk + 2 * t];
                ah[mt][2] = *(const uint32_t*)&As[0][r + g][kk + 8 + 2 * t];
                ah[mt][3] = *(const uint32_t*)&As[0][r + 8 + g][kk + 8 + 2 * t];
                al[mt][0] = *(const uint32_t*)&As[1][r + g][kk + 2 * t];
                al[mt][1] = *(const uint32_t*)&As[1][r + 8 + g][kk + 2 * t];
                al[mt][2] = *(const uint32_t*)&As[1][r + g][kk + 8 + 2 * t];
                al[mt][3] = *(const uint32_t*)&As[1][r + 8 + g][kk + 8 + 2 * t];
            }
            #pragma unroll
            for (int nt = 0; nt < 4; nt++) {
                uint32_t bh0, bh1, bl0, bl1;
                ldsm2t(bh0, bh1, &Bs[0][kk + (lane & 15)][wn * 32 + nt * 8]);
                ldsm2t(bl0, bl1, &Bs[1][kk + (lane & 15)][wn * 32 + nt * 8]);
                #pragma unroll
                for (int mt = 0; mt < 2; mt++) {
                    mma16816(c[mt][nt], ah[mt][0], ah[mt][1], ah[mt][2], ah[mt][3], bh0, bh1);
                    mma16816(c[mt][nt], ah[mt][0], ah[mt][1], ah[mt][2], ah[mt][3], bl0, bl1);
                    mma16816(c[mt][nt], al[mt][0], al[mt][1], al[mt][2], al[mt][3], bh0, bh1);
                }
            }
        }
        __syncthreads();
    }
    #pragma unroll
    for (int mt = 0; mt < 2; mt++) {
        #pragma unroll
        for (int nt = 0; nt < 4; nt++) {
            int rowA = m0 + wm * 32 + mt * 16 + g;
            int col = n0 + wn * 32 + nt * 8 + 2 * t;
            if (SPLIT_OUT) {
                uint32_t hi, lo;
                split2(c[mt][nt][0], c[mt][nt][1], hi, lo);
                *(uint32_t*)&Ch[(size_t)rowA * N + col] = hi;
                *(uint32_t*)&Cl[(size_t)rowA * N + col] = lo;
                split2(c[mt][nt][2], c[mt][nt][3], hi, lo);
                *(uint32_t*)&Ch[(size_t)(rowA + 8) * N + col] = hi;
                *(uint32_t*)&Cl[(size_t)(rowA + 8) * N + col] = lo;
            } else {
                *(float2*)&C[(size_t)rowA * N + col] =
                    make_float2(c[mt][nt][0], c[mt][nt][1]);
                *(float2*)&C[(size_t)(rowA + 8) * N + col] =
                    make_float2(c[mt][nt][2], c[mt][nt][3]);
            }
        }
    }
}

// ---------------------------------------------------------------------------
// Flash attention (R5 structure + Q fragments hoisted into registers).
// Grid (64 qtiles, 8 heads), 128 threads = 4 warps; warp owns 16 Q rows.
// Static smem (36.9 KB): K/V hi/lo tiles only -> 6 CTAs/SM.
// Mask exactly at kt == qt (64-row tiles, proven correct in R5).
// ---------------------------------------------------------------------------
#define ASM_ELE (64 * 72)

__global__ __launch_bounds__(128)
void mma_attn_kernel(const __nv_bfloat16* __restrict__ qh,
                     const __nv_bfloat16* __restrict__ ql,
                     __nv_bfloat16* __restrict__ aoh,
                     __nv_bfloat16* __restrict__ aol) {
    __shared__ __align__(16) __nv_bfloat16 Kh[ASM_ELE];
    __shared__ __align__(16) __nv_bfloat16 Kl[ASM_ELE];
    __shared__ __align__(16) __nv_bfloat16 Vh[ASM_ELE];
    __shared__ __align__(16) __nv_bfloat16 Vl[ASM_ELE];

    int qt = 63 - blockIdx.x;          // heavy tiles first
    int h = blockIdx.y;
    int tid = threadIdx.x;
    int wid = tid >> 5, lane = tid & 31;
    int g = lane >> 2, t = lane & 3;
    int r0 = wid * 16;
    int gA = qt * 64 + r0 + g;

    // Q fragments direct from gmem (loop-invariant, registers)
    uint32_t ahq[4][4], alq[4][4];
    {
        size_t rA = (size_t)gA * QKV_N + h * DHEAD;
        size_t rB = (size_t)(gA + 8) * QKV_N + h * DHEAD;
        #pragma unroll
        for (int d16 = 0; d16 < 4; d16++) {
            int cA = d16 * 16 + 2 * t, cB = d16 * 16 + 8 + 2 * t;
            ahq[d16][0] = *(const uint32_t*)&qh[rA + cA];
            ahq[d16][1] = *(const uint32_t*)&qh[rB + cA];
            ahq[d16][2] = *(const uint32_t*)&qh[rA + cB];
            ahq[d16][3] = *(const uint32_t*)&qh[rB + cB];
            alq[d16][0] = *(const uint32_t*)&ql[rA + cA];
            alq[d16][1] = *(const uint32_t*)&ql[rB + cA];
            alq[d16][2] = *(const uint32_t*)&ql[rA + cB];
            alq[d16][3] = *(const uint32_t*)&ql[rB + cB];
        }
    }

    float o[8][4];
    #pragma unroll
    for (int nt = 0; nt < 8; nt++)
        #pragma unroll
        for (int e = 0; e < 4; e++) o[nt][e] = 0.f;
    float m[2] = {-1e30f, -1e30f}, l[2] = {0.f, 0.f};

    for (int kt = 0; kt <= qt; kt++) {
        __syncthreads();
        for (int p = tid; p < 512; p += 128) {
            int rr = p >> 3, c8 = (p & 7) * 8;
            size_t base = (size_t)(kt * 64 + rr) * QKV_N + h * DHEAD + c8;
            *(uint4*)&Kh[rr * 72 + c8] = *(const uint4*)&qh[base + DINNER];
            *(uint4*)&Kl[rr * 72 + c8] = *(const uint4*)&ql[base + DINNER];
            *(uint4*)&Vh[rr * 72 + c8] = *(const uint4*)&qh[base + 2 * DINNER];
            *(uint4*)&Vl[rr * 72 + c8] = *(const uint4*)&ql[base + 2 * DINNER];
        }
        __syncthreads();

        float sc[8][4];
        #pragma unroll
        for (int nt = 0; nt < 8; nt++)
            #pragma unroll
            for (int e = 0; e < 4; e++) sc[nt][e] = 0.f;

        #pragma unroll
        for (int d16 = 0; d16 < 4; d16++) {
            #pragma unroll
            for (int nt = 0; nt < 8; nt++) {
                uint32_t bh0 = *(const uint32_t*)&Kh[(nt * 8 + g) * 72 + d16 * 16 + 2 * t];
                uint32_t bh1 = *(const uint32_t*)&Kh[(nt * 8 + g) * 72 + d16 * 16 + 8 + 2 * t];
                uint32_t bl0 = *(const uint32_t*)&Kl[(nt * 8 + g) * 72 + d16 * 16 + 2 * t];
                uint32_t bl1 = *(const uint32_t*)&Kl[(nt * 8 + g) * 72 + d16 * 16 + 8 + 2 * t];
                mma16816(sc[nt], ahq[d16][0], ahq[d16][1], ahq[d16][2], ahq[d16][3], bh0, bh1);
                mma16816(sc[nt], ahq[d16][0], ahq[d16][1], ahq[d16][2], ahq[d16][3], bl0, bl1);
                mma16816(sc[nt], alq[d16][0], alq[d16][1], alq[d16][2], alq[d16][3], bh0, bh1);
            }
        }

        #pragma unroll
        for (int nt = 0; nt < 8; nt++)
            #pragma unroll
            for (int e = 0; e < 4; e++) sc[nt][e] *= 8.f;

        if (kt == qt) {   // diagonal tile: causal mask
            #pragma unroll
            for (int nt = 0; nt < 8; nt++) {
                int colb = nt * 8 + 2 * t;
                int rA = r0 + g, rB = r0 + 8 + g;
                if (colb > rA)     sc[nt][0] = -1e30f;
                if (colb + 1 > rA) sc[nt][1] = -1e30f;
                if (colb > rB)     sc[nt][2] = -1e30f;
                if (colb + 1 > rB) sc[nt][3] = -1e30f;
            }
        }

        #pragma unroll
        for (int hf = 0; hf < 2; hf++) {
            float mx = -1e30f;
            #pragma unroll
            for (int nt = 0; nt < 8; nt++) {
                mx = fmaxf(mx, sc[nt][2 * hf]);
                mx = fmaxf(mx, sc[nt][2 * hf + 1]);
            }
            mx = fmaxf(mx, __shfl_xor_sync(0xffffffffu, mx, 1));
            mx = fmaxf(mx, __shfl_xor_sync(0xffffffffu, mx, 2));
            float mnew = fmaxf(m[hf], mx);
            float corr = __expf(m[hf] - mnew);
            m[hf] = mnew;
            float sum = 0.f;
            #pragma unroll
            for (int nt = 0; nt < 8; nt++) {
                float p0 = __expf(sc[nt][2 * hf] - mnew);
                float p1 = __expf(sc[nt][2 * hf + 1] - mnew);
                sc[nt][2 * hf] = p0;
                sc[nt][2 * hf + 1] = p1;
                sum += p0 + p1;
            }
            sum += __shfl_xor_sync(0xffffffffu, sum, 1);
            sum += __shfl_xor_sync(0xffffffffu, sum, 2);
            l[hf] = l[hf] * corr + sum;
            #pragma unroll
            for (int nt = 0; nt < 8; nt++) {
                o[nt][2 * hf] *= corr;
                o[nt][2 * hf + 1] *= corr;
            }
        }

        uint32_t phf[4][4], plf[4][4];
        #pragma unroll
        for (int kk = 0; kk < 4; kk++) {
            split2(sc[2 * kk][0], sc[2 * kk][1], phf[kk][0], plf[kk][0]);
            split2(sc[2 * kk][2], sc[2 * kk][3], phf[kk][1], plf[kk][1]);
            split2(sc[2 * kk + 1][0], sc[2 * kk + 1][1], phf[kk][2], plf[kk][2]);
            split2(sc[2 * kk + 1][2], sc[2 * kk + 1][3], phf[kk][3], plf[kk][3]);
        }

        #pragma unroll
        for (int nt = 0; nt < 8; nt++) {
            #pragma unroll
            for (int kk = 0; kk < 4; kk++) {
                uint32_t vh0, vh1, vl0, vl1;
                ldsm2t(vh0, vh1, &Vh[(kk * 16 + (lane & 15)) * 72 + nt * 8]);
                ldsm2t(vl0, vl1, &Vl[(kk * 16 + (lane & 15)) * 72 + nt * 8]);
                mma16816(o[nt], phf[kk][0], phf[kk][1], phf[kk][2], phf[kk][3], vh0, vh1);
                mma16816(o[nt], phf[kk][0], phf[kk][1], phf[kk][2], phf[kk][3], vl0, vl1);
                mma16816(o[nt], plf[kk][0], plf[kk][1], plf[kk][2], plf[kk][3], vh0, vh1);
            }
        }
    }

    float inv0 = 1.f / l[0], inv1 = 1.f / l[1];
    #pragma unroll
    for (int nt = 0; nt < 8; nt++) {
        int col = h * DHEAD + nt * 8 + 2 * t;
        size_t rA = (size_t)gA * DINNER + col;
        size_t rB = (size_t)(gA + 8) * DINNER + col;
        uint32_t hi, lo;
        split2(o[nt][0] * inv0, o[nt][1] * inv0, hi, lo);
        *(uint32_t*)&aoh[rA] = hi;
        *(uint32_t*)&aol[rA] = lo;
        split2(o[nt][2] * inv1, o[nt][3] * inv1, hi, lo);
        *(uint32_t*)&aoh[rB] = hi;
        *(uint32_t*)&aol[rB] = lo;
    }
}

// ---------------------------------------------------------------------------
extern "C" void kernel_launch(void* const* d_in, const int* in_sizes, int n_in,
                              void* d_out, int out_size) {
    const float* x     = (const float*)d_in[0];
    const float* gamma = (const float*)d_in[1];
    const float* w_qkv = (const float*)d_in[2];
    const float* w_out = (const float*)d_in[3];
    float* out = (float*)d_out;

    __nv_bfloat16 *xh, *xl, *wqh, *wql, *woh, *wol, *qkvh, *qkvl, *aoh, *aol;
    cudaGetSymbolAddress((void**)&xh, g_xh);
    cudaGetSymbolAddress((void**)&xl, g_xl);
    cudaGetSymbolAddress((void**)&wqh, g_wqh);
    cudaGetSymbolAddress((void**)&wql, g_wql);
    cudaGetSymbolAddress((void**)&woh, g_woh);
    cudaGetSymbolAddress((void**)&wol, g_wol);
    cudaGetSymbolAddress((void**)&qkvh, g_qkvh);
    cudaGetSymbolAddress((void**)&qkvl, g_qkvl);
    cudaGetSymbolAddress((void**)&aoh, g_aoh);
    cudaGetSymbolAddress((void**)&aol, g_aol);

    rms_scale_kernel<<<N_TOK, 256>>>(x);
    split_x_kernel<<<(N_TOK * DIM / 4) / 256, 256>>>((const float4*)x, gamma);
    split_w_kernel<<<(DIM * QKV_N / 4) / 256, 256>>>((const float4*)w_qkv, wqh, wql);
    split_w_kernel<<<(DINNER * DIM / 4) / 256, 256>>>((const float4*)w_out, woh, wol);

    mma_gemm_kernel<true><<<dim3(QKV_N / 64, N_TOK / 128), 256>>>(
        xh, xl, wqh, wql, nullptr, qkvh, qkvl, N_TOK, QKV_N, DIM);

    mma_attn_kernel<<<dim3(64, 8), 128>>>(qkvh, qkvl, aoh, aol);

    mma_gemm_kernel<false><<<dim3(DIM / 64, N_TOK / 128), 256>>>(
        aoh, aol, woh, wol, out, nullptr, nullptr, N_TOK, DIM, DINNER);
}

// round 10
// speedup vs baseline: 1.2176x; 1.0067x over previous
#include <cuda_runtime.h>
#include <cuda_bf16.h>
#include <math.h>
#include <stdint.h>

#define N_TOK   4096
#define DIM     1024
#define HEADS   8
#define DHEAD   64
#define DINNER  512
#define QKV_N   1536

// Scratch (allocation-free rule: __device__ globals)
__device__ float g_scale[N_TOK];
__device__ __nv_bfloat16 g_xh[(size_t)N_TOK * DIM],     g_xl[(size_t)N_TOK * DIM];
__device__ __nv_bfloat16 g_wqh[(size_t)DIM * QKV_N],    g_wql[(size_t)DIM * QKV_N];
__device__ __nv_bfloat16 g_woh[(size_t)DINNER * DIM],   g_wol[(size_t)DINNER * DIM];
__device__ __nv_bfloat16 g_qkvh[(size_t)N_TOK * QKV_N], g_qkvl[(size_t)N_TOK * QKV_N];
__device__ __nv_bfloat16 g_aoh[(size_t)N_TOK * DINNER], g_aol[(size_t)N_TOK * DINNER];

// ---------------------------------------------------------------------------
// Helpers
// ---------------------------------------------------------------------------
__device__ __forceinline__ void mma16816(float* c,
    uint32_t a0, uint32_t a1, uint32_t a2, uint32_t a3,
    uint32_t b0, uint32_t b1) {
    asm volatile(
        "mma.sync.aligned.m16n8k16.row.col.f32.bf16.bf16.f32 "
        "{%0,%1,%2,%3}, {%4,%5,%6,%7}, {%8,%9}, {%0,%1,%2,%3};"
        : "+f"(c[0]), "+f"(c[1]), "+f"(c[2]), "+f"(c[3])
        : "r"(a0), "r"(a1), "r"(a2), "r"(a3), "r"(b0), "r"(b1));
}
__device__ __forceinline__ void ldsm2t(uint32_t& r0, uint32_t& r1, const void* p) {
    uint32_t a = (uint32_t)__cvta_generic_to_shared(p);
    asm volatile("ldmatrix.sync.aligned.m8n8.x2.trans.shared.b16 {%0,%1}, [%2];"
                 : "=r"(r0), "=r"(r1) : "r"(a));
}
__device__ __forceinline__ void split2(float v0, float v1,
                                       uint32_t& hi, uint32_t& lo) {
    __nv_bfloat16 h0 = __float2bfloat16_rn(v0);
    __nv_bfloat16 h1 = __float2bfloat16_rn(v1);
    __nv_bfloat16 l0 = __float2bfloat16_rn(v0 - __bfloat162float(h0));
    __nv_bfloat16 l1 = __float2bfloat16_rn(v1 - __bfloat162float(h1));
    __nv_bfloat162 hp; hp.x = h0; hp.y = h1;
    __nv_bfloat162 lp; lp.x = l0; lp.y = l1;
    hi = *(uint32_t*)&hp;
    lo = *(uint32_t*)&lp;
}
__device__ __forceinline__ void cp16(uint32_t d, const void* s) {
    asm volatile("cp.async.cg.shared.global [%0], [%1], 16;" :: "r"(d), "l"(s));
}
__device__ __forceinline__ void cpcommit() { asm volatile("cp.async.commit_group;" ::: "memory"); }
__device__ __forceinline__ void cpwait0()  { asm volatile("cp.async.wait_group 0;" ::: "memory"); }
__device__ __forceinline__ void cpwait1()  { asm volatile("cp.async.wait_group 1;" ::: "memory"); }

// ---------------------------------------------------------------------------
// Kernel 1: fused rmsnorm + gamma + bf16 hi/lo split of x.
// One block per row; each thread owns 4 elements across reduce + split.
// ---------------------------------------------------------------------------
__global__ __launch_bounds__(256)
void rms_split_x_kernel(const float4* __restrict__ x,
                        const float* __restrict__ gamma) {
    int row = blockIdx.x;
    float4 v = x[(size_t)row * 256 + threadIdx.x];
    float s = v.x * v.x + v.y * v.y + v.z * v.z + v.w * v.w;
    #pragma unroll
    for (int o = 16; o; o >>= 1) s += __shfl_xor_sync(0xffffffffu, s, o);
    __shared__ float ws[8];
    if ((threadIdx.x & 31) == 0) ws[threadIdx.x >> 5] = s;
    __syncthreads();
    float t = 0.f;
    #pragma unroll
    for (int i = 0; i < 8; i++) t += ws[i];
    float sc = 32.0f / fmaxf(sqrtf(t), 1e-12f);

    int col = threadIdx.x * 4;
    float4 gm = *(const float4*)(gamma + col);
    uint32_t h0, l0, h1, l1;
    split2(v.x * sc * gm.x, v.y * sc * gm.y, h0, l0);
    split2(v.z * sc * gm.z, v.w * sc * gm.w, h1, l1);
    size_t o4 = (size_t)row * DIM + col;
    *(uint2*)&g_xh[o4] = make_uint2(h0, h1);
    *(uint2*)&g_xl[o4] = make_uint2(l0, l1);
}

__global__ void split_w_kernel(const float4* __restrict__ w,
                               __nv_bfloat16* __restrict__ hi,
                               __nv_bfloat16* __restrict__ lo) {
    int i = blockIdx.x * 256 + threadIdx.x;
    float4 v = w[i];
    uint32_t h0, l0, h1, l1;
    split2(v.x, v.y, h0, l0);
    split2(v.z, v.w, h1, l1);
    *(uint2*)&hi[(size_t)4 * i] = make_uint2(h0, h1);
    *(uint2*)&lo[(size_t)4 * i] = make_uint2(l0, l1);
}

// ---------------------------------------------------------------------------
// bf16-split HMMA GEMM: C = (Ah+Al) @ (Bh+Bl), 3-product emulation.
// R5 tile structure (128x64, BK=32, 8 warps, warp tile 32x32) with
// cp.async 2-stage double buffering (59.4 KB dynamic smem, 3 CTAs/SM).
// Stage layout (elems): Ah[128*40] | Al[128*40] | Bh[32*72] | Bl[32*72]
// ---------------------------------------------------------------------------
#define GA_ELE (128 * 40)
#define GB_ELE (32 * 72)
#define GSTAGE_ELE (2 * GA_ELE + 2 * GB_ELE)             // 14848 elems
#define GEMM_SMEM (2 * GSTAGE_ELE * 2)                   // 59392 bytes

template <bool SPLIT_OUT>
__global__ __launch_bounds__(256)
void mma_gemm_kernel(const __nv_bfloat16* __restrict__ Ah,
                     const __nv_bfloat16* __restrict__ Al,
                     const __nv_bfloat16* __restrict__ Bh,
                     const __nv_bfloat16* __restrict__ Bl,
                     float* __restrict__ C,
                     __nv_bfloat16* __restrict__ Ch,
                     __nv_bfloat16* __restrict__ Cl,
                     int M, int N, int K) {
    extern __shared__ __align__(16) __nv_bfloat16 smg[];
    uint32_t smg_u = (uint32_t)__cvta_generic_to_shared(smg);
    int tid = threadIdx.x;
    int wid = tid >> 5, lane = tid & 31;
    int g = lane >> 2, t = lane & 3;
    int wm = wid & 3, wn = wid >> 2;
    int m0 = blockIdx.y * 128, n0 = blockIdx.x * 64;

    // loader indices (16B granules)
    int a0r = tid >> 2,        a0k = (tid & 3) * 8;      // covers 128x32 half 1
    int a1r = (tid + 256) >> 2, a1k = ((tid + 256) & 3) * 8;
    int br = tid >> 3,         bn = (tid & 7) * 8;

    #define G_LOAD(buf_, k0_) do {                                              \
        uint32_t sb = smg_u + (buf_) * (GSTAGE_ELE * 2);                        \
        cp16(sb + (a0r * 40 + a0k) * 2,                                         \
             Ah + (size_t)(m0 + a0r) * K + (k0_) + a0k);                        \
        cp16(sb + (a1r * 40 + a1k) * 2,                                         \
             Ah + (size_t)(m0 + a1r) * K + (k0_) + a1k);                        \
        cp16(sb + (GA_ELE + a0r * 40 + a0k) * 2,                                \
             Al + (size_t)(m0 + a0r) * K + (k0_) + a0k);                        \
        cp16(sb + (GA_ELE + a1r * 40 + a1k) * 2,                                \
             Al + (size_t)(m0 + a1r) * K + (k0_) + a1k);                        \
        cp16(sb + (2 * GA_ELE + br * 72 + bn) * 2,                              \
             Bh + (size_t)((k0_) + br) * N + n0 + bn);                          \
        cp16(sb + (2 * GA_ELE + GB_ELE + br * 72 + bn) * 2,                     \
             Bl + (size_t)((k0_) + br) * N + n0 + bn);                          \
        cpcommit();                                                             \
    } while (0)

    float c[2][4][4];
    #pragma unroll
    for (int mt = 0; mt < 2; mt++)
        #pragma unroll
        for (int nt = 0; nt < 4; nt++)
            #pragma unroll
            for (int e = 0; e < 4; e++) c[mt][nt][e] = 0.f;

    const int S = K / 32;
    G_LOAD(0, 0);
    for (int s = 0; s < S; s++) {
        if (s + 1 < S) { G_LOAD((s + 1) & 1, (s + 1) * 32); cpwait1(); }
        else           { cpwait0(); }
        __syncthreads();

        const __nv_bfloat16* stg = smg + (s & 1) * GSTAGE_ELE;
        const __nv_bfloat16* As0 = stg;
        const __nv_bfloat16* As1 = stg + GA_ELE;
        const __nv_bfloat16* Bs0 = stg + 2 * GA_ELE;
        const __nv_bfloat16* Bs1 = stg + 2 * GA_ELE + GB_ELE;

        #pragma unroll
        for (int kk = 0; kk < 32; kk += 16) {
            uint32_t ah[2][4], al[2][4];
            #pragma unroll
            for (int mt = 0; mt < 2; mt++) {
                int r = wm * 32 + mt * 16;
                ah[mt][0] = *(const uint32_t*)&As0[(r + g) * 40 + kk + 2 * t];
                ah[mt][1] = *(const uint32_t*)&As0[(r + 8 + g) * 40 + kk + 2 * t];
                ah[mt][2] = *(const uint32_t*)&As0[(r + g) * 40 + kk + 8 + 2 * t];
                ah[mt][3] = *(const uint32_t*)&As0[(r + 8 + g) * 40 + kk + 8 + 2 * t];
                al[mt][0] = *(const uint32_t*)&As1[(r + g) * 40 + kk + 2 * t];
                al[mt][1] = *(const uint32_t*)&As1[(r + 8 + g) * 40 + kk + 2 * t];
                al[mt][2] = *(const uint32_t*)&As1[(r + g) * 40 + kk + 8 + 2 * t];
                al[mt][3] = *(const uint32_t*)&As1[(r + 8 + g) * 40 + kk + 8 + 2 * t];
            }
            #pragma unroll
            for (int nt = 0; nt < 4; nt++) {
                uint32_t bh0, bh1, bl0, bl1;
                ldsm2t(bh0, bh1, &Bs0[(kk + (lane & 15)) * 72 + wn * 32 + nt * 8]);
                ldsm2t(bl0, bl1, &Bs1[(kk + (lane & 15)) * 72 + wn * 32 + nt * 8]);
                #pragma unroll
                for (int mt = 0; mt < 2; mt++) {
                    mma16816(c[mt][nt], ah[mt][0], ah[mt][1], ah[mt][2], ah[mt][3], bh0, bh1);
                    mma16816(c[mt][nt], ah[mt][0], ah[mt][1], ah[mt][2], ah[mt][3], bl0, bl1);
                    mma16816(c[mt][nt], al[mt][0], al[mt][1], al[mt][2], al[mt][3], bh0, bh1);
                }
            }
        }
        __syncthreads();   // free this stage for the load at iter s+1
    }

    #pragma unroll
    for (int mt = 0; mt < 2; mt++) {
        #pragma unroll
        for (int nt = 0; nt < 4; nt++) {
            int rowA = m0 + wm * 32 + mt * 16 + g;
            int col = n0 + wn * 32 + nt * 8 + 2 * t;
            if (SPLIT_OUT) {
                uint32_t hi, lo;
                split2(c[mt][nt][0], c[mt][nt][1], hi, lo);
                *(uint32_t*)&Ch[(size_t)rowA * N + col] = hi;
                *(uint32_t*)&Cl[(size_t)rowA * N + col] = lo;
                split2(c[mt][nt][2], c[mt][nt][3], hi, lo);
                *(uint32_t*)&Ch[(size_t)(rowA + 8) * N + col] = hi;
                *(uint32_t*)&Cl[(size_t)(rowA + 8) * N + col] = lo;
            } else {
                *(float2*)&C[(size_t)rowA * N + col] =
                    make_float2(c[mt][nt][0], c[mt][nt][1]);
                *(float2*)&C[(size_t)(rowA + 8) * N + col] =
                    make_float2(c[mt][nt][2], c[mt][nt][3]);
            }
        }
    }
    #undef G_LOAD
}

// ---------------------------------------------------------------------------
// Flash attention (R9 version, unchanged): HMMA bf16-split, 64-row Q tiles,
// 128 thr = 4 warps, Q frags in registers, static 36.9 KB smem.
// ---------------------------------------------------------------------------
#define ASM_ELE (64 * 72)

__global__ __launch_bounds__(128)
void mma_attn_kernel(const __nv_bfloat16* __restrict__ qh,
                     const __nv_bfloat16* __restrict__ ql,
                     __nv_bfloat16* __restrict__ aoh,
                     __nv_bfloat16* __restrict__ aol) {
    __shared__ __align__(16) __nv_bfloat16 Kh[ASM_ELE];
    __shared__ __align__(16) __nv_bfloat16 Kl[ASM_ELE];
    __shared__ __align__(16) __nv_bfloat16 Vh[ASM_ELE];
    __shared__ __align__(16) __nv_bfloat16 Vl[ASM_ELE];

    int qt = 63 - blockIdx.x;          // heavy tiles first
    int h = blockIdx.y;
    int tid = threadIdx.x;
    int wid = tid >> 5, lane = tid & 31;
    int g = lane >> 2, t = lane & 3;
    int r0 = wid * 16;
    int gA = qt * 64 + r0 + g;

    uint32_t ahq[4][4], alq[4][4];
    {
        size_t rA = (size_t)gA * QKV_N + h * DHEAD;
        size_t rB = (size_t)(gA + 8) * QKV_N + h * DHEAD;
        #pragma unroll
        for (int d16 = 0; d16 < 4; d16++) {
            int cA = d16 * 16 + 2 * t, cB = d16 * 16 + 8 + 2 * t;
            ahq[d16][0] = *(const uint32_t*)&qh[rA + cA];
            ahq[d16][1] = *(const uint32_t*)&qh[rB + cA];
            ahq[d16][2] = *(const uint32_t*)&qh[rA + cB];
            ahq[d16][3] = *(const uint32_t*)&qh[rB + cB];
            alq[d16][0] = *(const uint32_t*)&ql[rA + cA];
            alq[d16][1] = *(const uint32_t*)&ql[rB + cA];
            alq[d16][2] = *(const uint32_t*)&ql[rA + cB];
            alq[d16][3] = *(const uint32_t*)&ql[rB + cB];
        }
    }

    float o[8][4];
    #pragma unroll
    for (int nt = 0; nt < 8; nt++)
        #pragma unroll
        for (int e = 0; e < 4; e++) o[nt][e] = 0.f;
    float m[2] = {-1e30f, -1e30f}, l[2] = {0.f, 0.f};

    for (int kt = 0; kt <= qt; kt++) {
        __syncthreads();
        for (int p = tid; p < 512; p += 128) {
            int rr = p >> 3, c8 = (p & 7) * 8;
            size_t base = (size_t)(kt * 64 + rr) * QKV_N + h * DHEAD + c8;
            *(uint4*)&Kh[rr * 72 + c8] = *(const uint4*)&qh[base + DINNER];
            *(uint4*)&Kl[rr * 72 + c8] = *(const uint4*)&ql[base + DINNER];
            *(uint4*)&Vh[rr * 72 + c8] = *(const uint4*)&qh[base + 2 * DINNER];
            *(uint4*)&Vl[rr * 72 + c8] = *(const uint4*)&ql[base + 2 * DINNER];
        }
        __syncthreads();

        float sc[8][4];
        #pragma unroll
        for (int nt = 0; nt < 8; nt++)
            #pragma unroll
            for (int e = 0; e < 4; e++) sc[nt][e] = 0.f;

        #pragma unroll
        for (int d16 = 0; d16 < 4; d16++) {
            #pragma unroll
            for (int nt = 0; nt < 8; nt++) {
                uint32_t bh0 = *(const uint32_t*)&Kh[(nt * 8 + g) * 72 + d16 * 16 + 2 * t];
                uint32_t bh1 = *(const uint32_t*)&Kh[(nt * 8 + g) * 72 + d16 * 16 + 8 + 2 * t];
                uint32_t bl0 = *(const uint32_t*)&Kl[(nt * 8 + g) * 72 + d16 * 16 + 2 * t];
                uint32_t bl1 = *(const uint32_t*)&Kl[(nt * 8 + g) * 72 + d16 * 16 + 8 + 2 * t];
                mma16816(sc[nt], ahq[d16][0], ahq[d16][1], ahq[d16][2], ahq[d16][3], bh0, bh1);
                mma16816(sc[nt], ahq[d16][0], ahq[d16][1], ahq[d16][2], ahq[d16][3], bl0, bl1);
                mma16816(sc[nt], alq[d16][0], alq[d16][1], alq[d16][2], alq[d16][3], bh0, bh1);
            }
        }

        #pragma unroll
        for (int nt = 0; nt < 8; nt++)
            #pragma unroll
            for (int e = 0; e < 4; e++) sc[nt][e] *= 8.f;

        if (kt == qt) {
            #pragma unroll
            for (int nt = 0; nt < 8; nt++) {
                int colb = nt * 8 + 2 * t;
                int rA = r0 + g, rB = r0 + 8 + g;
                if (colb > rA)     sc[nt][0] = -1e30f;
                if (colb + 1 > rA) sc[nt][1] = -1e30f;
                if (colb > rB)     sc[nt][2] = -1e30f;
                if (colb + 1 > rB) sc[nt][3] = -1e30f;
            }
        }

        #pragma unroll
        for (int hf = 0; hf < 2; hf++) {
            float mx = -1e30f;
            #pragma unroll
            for (int nt = 0; nt < 8; nt++) {
                mx = fmaxf(mx, sc[nt][2 * hf]);
                mx = fmaxf(mx, sc[nt][2 * hf + 1]);
            }
            mx = fmaxf(mx, __shfl_xor_sync(0xffffffffu, mx, 1));
            mx = fmaxf(mx, __shfl_xor_sync(0xffffffffu, mx, 2));
            float mnew = fmaxf(m[hf], mx);
            float corr = __expf(m[hf] - mnew);
            m[hf] = mnew;
            float sum = 0.f;
            #pragma unroll
            for (int nt = 0; nt < 8; nt++) {
                float p0 = __expf(sc[nt][2 * hf] - mnew);
                float p1 = __expf(sc[nt][2 * hf + 1] - mnew);
                sc[nt][2 * hf] = p0;
                sc[nt][2 * hf + 1] = p1;
                sum += p0 + p1;
            }
            sum += __shfl_xor_sync(0xffffffffu, sum, 1);
            sum += __shfl_xor_sync(0xffffffffu, sum, 2);
            l[hf] = l[hf] * corr + sum;
            #pragma unroll
            for (int nt = 0; nt < 8; nt++) {
                o[nt][2 * hf] *= corr;
                o[nt][2 * hf + 1] *= corr;
            }
        }

        uint32_t phf[4][4], plf[4][4];
        #pragma unroll
        for (int kk = 0; kk < 4; kk++) {
            split2(sc[2 * kk][0], sc[2 * kk][1], phf[kk][0], plf[kk][0]);
            split2(sc[2 * kk][2], sc[2 * kk][3], phf[kk][1], plf[kk][1]);
            split2(sc[2 * kk + 1][0], sc[2 * kk + 1][1], phf[kk][2], plf[kk][2]);
            split2(sc[2 * kk + 1][2], sc[2 * kk + 1][3], phf[kk][3], plf[kk][3]);
        }

        #pragma unroll
        for (int nt = 0; nt < 8; nt++) {
            #pragma unroll
            for (int kk = 0; kk < 4; kk++) {
                uint32_t vh0, vh1, vl0, vl1;
                ldsm2t(vh0, vh1, &Vh[(kk * 16 + (lane & 15)) * 72 + nt * 8]);
                ldsm2t(vl0, vl1, &Vl[(kk * 16 + (lane & 15)) * 72 + nt * 8]);
                mma16816(o[nt], phf[kk][0], phf[kk][1], phf[kk][2], phf[kk][3], vh0, vh1);
                mma16816(o[nt], phf[kk][0], phf[kk][1], phf[kk][2], phf[kk][3], vl0, vl1);
                mma16816(o[nt], plf[kk][0], plf[kk][1], plf[kk][2], plf[kk][3], vh0, vh1);
            }
        }
    }

    float inv0 = 1.f / l[0], inv1 = 1.f / l[1];
    #pragma unroll
    for (int nt = 0; nt < 8; nt++) {
        int col = h * DHEAD + nt * 8 + 2 * t;
        size_t rA = (size_t)gA * DINNER + col;
        size_t rB = (size_t)(gA + 8) * DINNER + col;
        uint32_t hi, lo;
        split2(o[nt][0] * inv0, o[nt][1] * inv0, hi, lo);
        *(uint32_t*)&aoh[rA] = hi;
        *(uint32_t*)&aol[rA] = lo;
        split2(o[nt][2] * inv1, o[nt][3] * inv1, hi, lo);
        *(uint32_t*)&aoh[rB] = hi;
        *(uint32_t*)&aol[rB] = lo;
    }
}

// ---------------------------------------------------------------------------
extern "C" void kernel_launch(void* const* d_in, const int* in_sizes, int n_in,
                              void* d_out, int out_size) {
    const float* x     = (const float*)d_in[0];
    const float* gamma = (const float*)d_in[1];
    const float* w_qkv = (const float*)d_in[2];
    const float* w_out = (const float*)d_in[3];
    float* out = (float*)d_out;

    __nv_bfloat16 *xh, *xl, *wqh, *wql, *woh, *wol, *qkvh, *qkvl, *aoh, *aol;
    cudaGetSymbolAddress((void**)&xh, g_xh);
    cudaGetSymbolAddress((void**)&xl, g_xl);
    cudaGetSymbolAddress((void**)&wqh, g_wqh);
    cudaGetSymbolAddress((void**)&wql, g_wql);
    cudaGetSymbolAddress((void**)&woh, g_woh);
    cudaGetSymbolAddress((void**)&wol, g_wol);
    cudaGetSymbolAddress((void**)&qkvh, g_qkvh);
    cudaGetSymbolAddress((void**)&qkvl, g_qkvl);
    cudaGetSymbolAddress((void**)&aoh, g_aoh);
    cudaGetSymbolAddress((void**)&aol, g_aol);

    cudaFuncSetAttribute(mma_gemm_kernel<true>,
                         cudaFuncAttributeMaxDynamicSharedMemorySize, GEMM_SMEM);
    cudaFuncSetAttribute(mma_gemm_kernel<false>,
                         cudaFuncAttributeMaxDynamicSharedMemorySize, GEMM_SMEM);

    rms_split_x_kernel<<<N_TOK, 256>>>((const float4*)x, gamma);
    split_w_kernel<<<(DIM * QKV_N / 4) / 256, 256>>>((const float4*)w_qkv, wqh, wql);
    split_w_kernel<<<(DINNER * DIM / 4) / 256, 256>>>((const float4*)w_out, woh, wol);

    mma_gemm_kernel<true><<<dim3(QKV_N / 64, N_TOK / 128), 256, GEMM_SMEM>>>(
        xh, xl, wqh, wql, nullptr, qkvh, qkvl, N_TOK, QKV_N, DIM);

    mma_attn_kernel<<<dim3(64, 8), 128>>>(qkvh, qkvl, aoh, aol);

    mma_gemm_kernel<false><<<dim3(DIM / 64, N_TOK / 128), 256, GEMM_SMEM>>>(
        aoh, aol, woh, wol, out, nullptr, nullptr, N_TOK, DIM, DINNER);
}

// round 11
// speedup vs baseline: 1.3785x; 1.1321x over previous
#include <cuda_runtime.h>
#include <cuda_bf16.h>
#include <math.h>
#include <stdint.h>

#define N_TOK   4096
#define DIM     1024
#define HEADS   8
#define DHEAD   64
#define DINNER  512
#define QKV_N   1536

// Scratch (allocation-free rule: __device__ globals)
__device__ float g_scale[N_TOK];
__device__ __nv_bfloat16 g_xh[(size_t)N_TOK * DIM],     g_xl[(size_t)N_TOK * DIM];
__device__ __nv_bfloat16 g_wqh[(size_t)DIM * QKV_N],    g_wql[(size_t)DIM * QKV_N];
__device__ __nv_bfloat16 g_woh[(size_t)DINNER * DIM],   g_wol[(size_t)DINNER * DIM];
__device__ __nv_bfloat16 g_qkvh[(size_t)N_TOK * QKV_N], g_qkvl[(size_t)N_TOK * QKV_N];
__device__ __nv_bfloat16 g_aoh[(size_t)N_TOK * DINNER], g_aol[(size_t)N_TOK * DINNER];

// ---------------------------------------------------------------------------
// Helpers
// ---------------------------------------------------------------------------
__device__ __forceinline__ void mma16816(float* c,
    uint32_t a0, uint32_t a1, uint32_t a2, uint32_t a3,
    uint32_t b0, uint32_t b1) {
    asm volatile(
        "mma.sync.aligned.m16n8k16.row.col.f32.bf16.bf16.f32 "
        "{%0,%1,%2,%3}, {%4,%5,%6,%7}, {%8,%9}, {%0,%1,%2,%3};"
        : "+f"(c[0]), "+f"(c[1]), "+f"(c[2]), "+f"(c[3])
        : "r"(a0), "r"(a1), "r"(a2), "r"(a3), "r"(b0), "r"(b1));
}
// 4-tile ldmatrix, non-transposed: lanes 0-7/8-15/16-23/24-31 address tiles 0-3.
__device__ __forceinline__ void ldsm4(uint32_t& r0, uint32_t& r1,
                                      uint32_t& r2, uint32_t& r3, const void* p) {
    uint32_t a = (uint32_t)__cvta_generic_to_shared(p);
    asm volatile("ldmatrix.sync.aligned.m8n8.x4.shared.b16 {%0,%1,%2,%3}, [%4];"
                 : "=r"(r0), "=r"(r1), "=r"(r2), "=r"(r3) : "r"(a));
}
// 4-tile ldmatrix, transposed.
__device__ __forceinline__ void ldsm4t(uint32_t& r0, uint32_t& r1,
                                       uint32_t& r2, uint32_t& r3, const void* p) {
    uint32_t a = (uint32_t)__cvta_generic_to_shared(p);
    asm volatile("ldmatrix.sync.aligned.m8n8.x4.trans.shared.b16 {%0,%1,%2,%3}, [%4];"
                 : "=r"(r0), "=r"(r1), "=r"(r2), "=r"(r3) : "r"(a));
}
__device__ __forceinline__ void split2(float v0, float v1,
                                       uint32_t& hi, uint32_t& lo) {
    __nv_bfloat16 h0 = __float2bfloat16_rn(v0);
    __nv_bfloat16 h1 = __float2bfloat16_rn(v1);
    __nv_bfloat16 l0 = __float2bfloat16_rn(v0 - __bfloat162float(h0));
    __nv_bfloat16 l1 = __float2bfloat16_rn(v1 - __bfloat162float(h1));
    __nv_bfloat162 hp; hp.x = h0; hp.y = h1;
    __nv_bfloat162 lp; lp.x = l0; lp.y = l1;
    hi = *(uint32_t*)&hp;
    lo = *(uint32_t*)&lp;
}
__device__ __forceinline__ void cp16(uint32_t d, const void* s) {
    asm volatile("cp.async.cg.shared.global [%0], [%1], 16;" :: "r"(d), "l"(s));
}
__device__ __forceinline__ void cpcommit() { asm volatile("cp.async.commit_group;" ::: "memory"); }
__device__ __forceinline__ void cpwait0()  { asm volatile("cp.async.wait_group 0;" ::: "memory"); }
__device__ __forceinline__ void cpwait1()  { asm volatile("cp.async.wait_group 1;" ::: "memory"); }

// ---------------------------------------------------------------------------
// Kernel 1: fused rmsnorm + gamma + bf16 hi/lo split of x.
// ---------------------------------------------------------------------------
__global__ __launch_bounds__(256)
void rms_split_x_kernel(const float4* __restrict__ x,
                        const float* __restrict__ gamma) {
    int row = blockIdx.x;
    float4 v = x[(size_t)row * 256 + threadIdx.x];
    float s = v.x * v.x + v.y * v.y + v.z * v.z + v.w * v.w;
    #pragma unroll
    for (int o = 16; o; o >>= 1) s += __shfl_xor_sync(0xffffffffu, s, o);
    __shared__ float ws[8];
    if ((threadIdx.x & 31) == 0) ws[threadIdx.x >> 5] = s;
    __syncthreads();
    float t = 0.f;
    #pragma unroll
    for (int i = 0; i < 8; i++) t += ws[i];
    float sc = 32.0f / fmaxf(sqrtf(t), 1e-12f);

    int col = threadIdx.x * 4;
    float4 gm = *(const float4*)(gamma + col);
    uint32_t h0, l0, h1, l1;
    split2(v.x * sc * gm.x, v.y * sc * gm.y, h0, l0);
    split2(v.z * sc * gm.z, v.w * sc * gm.w, h1, l1);
    size_t o4 = (size_t)row * DIM + col;
    *(uint2*)&g_xh[o4] = make_uint2(h0, h1);
    *(uint2*)&g_xl[o4] = make_uint2(l0, l1);
}

__global__ void split_w_kernel(const float4* __restrict__ w,
                               __nv_bfloat16* __restrict__ hi,
                               __nv_bfloat16* __restrict__ lo) {
    int i = blockIdx.x * 256 + threadIdx.x;
    float4 v = w[i];
    uint32_t h0, l0, h1, l1;
    split2(v.x, v.y, h0, l0);
    split2(v.z, v.w, h1, l1);
    *(uint2*)&hi[(size_t)4 * i] = make_uint2(h0, h1);
    *(uint2*)&lo[(size_t)4 * i] = make_uint2(l0, l1);
}

// ---------------------------------------------------------------------------
// bf16-split HMMA GEMM: C = (Ah+Al) @ (Bh+Bl), 3-product emulation.
// 128x64 tile, BK=32, 8 warps (4m x 2n), warp tile 32x32, cp.async 2-stage.
// Operand fetch via ldmatrix.x4 (A non-trans, B trans).
// ---------------------------------------------------------------------------
#define GA_ELE (128 * 40)
#define GB_ELE (32 * 72)
#define GSTAGE_ELE (2 * GA_ELE + 2 * GB_ELE)
#define GEMM_SMEM (2 * GSTAGE_ELE * 2)

template <bool SPLIT_OUT>
__global__ __launch_bounds__(256)
void mma_gemm_kernel(const __nv_bfloat16* __restrict__ Ah,
                     const __nv_bfloat16* __restrict__ Al,
                     const __nv_bfloat16* __restrict__ Bh,
                     const __nv_bfloat16* __restrict__ Bl,
                     float* __restrict__ C,
                     __nv_bfloat16* __restrict__ Ch,
                     __nv_bfloat16* __restrict__ Cl,
                     int M, int N, int K) {
    extern __shared__ __align__(16) __nv_bfloat16 smg[];
    uint32_t smg_u = (uint32_t)__cvta_generic_to_shared(smg);
    int tid = threadIdx.x;
    int wid = tid >> 5, lane = tid & 31;
    int g = lane >> 2, t = lane & 3;
    int wm = wid & 3, wn = wid >> 2;
    int m0 = blockIdx.y * 128, n0 = blockIdx.x * 64;

    // ldmatrix lane->address components
    int arow = ((lane >> 3) & 1) * 8 + (lane & 7);   // A: tiles row-major within m16
    int acol = (lane >> 4) * 8;                       // A: k half
    int brow = lane & 15;                             // B trans: k row within 16
    int bcol = (lane >> 4) * 8;                       // B trans: n half

    // cp.async loader indices
    int a0r = tid >> 2,         a0k = (tid & 3) * 8;
    int a1r = (tid + 256) >> 2, a1k = ((tid + 256) & 3) * 8;
    int lbr = tid >> 3,         lbn = (tid & 7) * 8;

    #define G_LOAD(buf_, k0_) do {                                              \
        uint32_t sb = smg_u + (buf_) * (GSTAGE_ELE * 2);                        \
        cp16(sb + (a0r * 40 + a0k) * 2,                                         \
             Ah + (size_t)(m0 + a0r) * K + (k0_) + a0k);                        \
        cp16(sb + (a1r * 40 + a1k) * 2,                                         \
             Ah + (size_t)(m0 + a1r) * K + (k0_) + a1k);                        \
        cp16(sb + (GA_ELE + a0r * 40 + a0k) * 2,                                \
             Al + (size_t)(m0 + a0r) * K + (k0_) + a0k);                        \
        cp16(sb + (GA_ELE + a1r * 40 + a1k) * 2,                                \
             Al + (size_t)(m0 + a1r) * K + (k0_) + a1k);                        \
        cp16(sb + (2 * GA_ELE + lbr * 72 + lbn) * 2,                            \
             Bh + (size_t)((k0_) + lbr) * N + n0 + lbn);                        \
        cp16(sb + (2 * GA_ELE + GB_ELE + lbr * 72 + lbn) * 2,                   \
             Bl + (size_t)((k0_) + lbr) * N + n0 + lbn);                        \
        cpcommit();                                                             \
    } while (0)

    float c[2][4][4];
    #pragma unroll
    for (int mt = 0; mt < 2; mt++)
        #pragma unroll
        for (int nt = 0; nt < 4; nt++)
            #pragma unroll
            for (int e = 0; e < 4; e++) c[mt][nt][e] = 0.f;

    const int S = K / 32;
    G_LOAD(0, 0);
    for (int s = 0; s < S; s++) {
        if (s + 1 < S) { G_LOAD((s + 1) & 1, (s + 1) * 32); cpwait1(); }
        else           { cpwait0(); }
        __syncthreads();

        const __nv_bfloat16* stg = smg + (s & 1) * GSTAGE_ELE;
        const __nv_bfloat16* As0 = stg;
        const __nv_bfloat16* As1 = stg + GA_ELE;
        const __nv_bfloat16* Bs0 = stg + 2 * GA_ELE;
        const __nv_bfloat16* Bs1 = stg + 2 * GA_ELE + GB_ELE;

        #pragma unroll
        for (int kk = 0; kk < 32; kk += 16) {
            uint32_t ah[2][4], al[2][4];
            #pragma unroll
            for (int mt = 0; mt < 2; mt++) {
                int r = wm * 32 + mt * 16;
                ldsm4(ah[mt][0], ah[mt][1], ah[mt][2], ah[mt][3],
                      &As0[(r + arow) * 40 + kk + acol]);
                ldsm4(al[mt][0], al[mt][1], al[mt][2], al[mt][3],
                      &As1[(r + arow) * 40 + kk + acol]);
            }
            #pragma unroll
            for (int p2 = 0; p2 < 2; p2++) {       // nt pairs {0,1},{2,3}
                uint32_t bh0, bh1, bh2, bh3, bl0, bl1, bl2, bl3;
                ldsm4t(bh0, bh1, bh2, bh3,
                       &Bs0[(kk + brow) * 72 + wn * 32 + p2 * 16 + bcol]);
                ldsm4t(bl0, bl1, bl2, bl3,
                       &Bs1[(kk + brow) * 72 + wn * 32 + p2 * 16 + bcol]);
                #pragma unroll
                for (int mt = 0; mt < 2; mt++) {
                    mma16816(c[mt][2*p2],   ah[mt][0], ah[mt][1], ah[mt][2], ah[mt][3], bh0, bh1);
                    mma16816(c[mt][2*p2],   ah[mt][0], ah[mt][1], ah[mt][2], ah[mt][3], bl0, bl1);
                    mma16816(c[mt][2*p2],   al[mt][0], al[mt][1], al[mt][2], al[mt][3], bh0, bh1);
                    mma16816(c[mt][2*p2+1], ah[mt][0], ah[mt][1], ah[mt][2], ah[mt][3], bh2, bh3);
                    mma16816(c[mt][2*p2+1], ah[mt][0], ah[mt][1], ah[mt][2], ah[mt][3], bl2, bl3);
                    mma16816(c[mt][2*p2+1], al[mt][0], al[mt][1], al[mt][2], al[mt][3], bh2, bh3);
                }
            }
        }
        __syncthreads();
    }

    #pragma unroll
    for (int mt = 0; mt < 2; mt++) {
        #pragma unroll
        for (int nt = 0; nt < 4; nt++) {
            int rowA = m0 + wm * 32 + mt * 16 + g;
            int col = n0 + wn * 32 + nt * 8 + 2 * t;
            if (SPLIT_OUT) {
                uint32_t hi, lo;
                split2(c[mt][nt][0], c[mt][nt][1], hi, lo);
                *(uint32_t*)&Ch[(size_t)rowA * N + col] = hi;
                *(uint32_t*)&Cl[(size_t)rowA * N + col] = lo;
                split2(c[mt][nt][2], c[mt][nt][3], hi, lo);
                *(uint32_t*)&Ch[(size_t)(rowA + 8) * N + col] = hi;
                *(uint32_t*)&Cl[(size_t)(rowA + 8) * N + col] = lo;
            } else {
                *(float2*)&C[(size_t)rowA * N + col] =
                    make_float2(c[mt][nt][0], c[mt][nt][1]);
                *(float2*)&C[(size_t)(rowA + 8) * N + col] =
                    make_float2(c[mt][nt][2], c[mt][nt][3]);
            }
        }
    }
    #undef G_LOAD
}

// ---------------------------------------------------------------------------
// Flash attention: HMMA bf16-split, 64-row Q tiles, 128 thr = 4 warps,
// Q frags in registers, static 36.9 KB smem (6 CTAs/SM).
// K-frags via ldmatrix.x4 non-trans; V-frags via ldmatrix.x4.trans.
// ---------------------------------------------------------------------------
#define ASM_ELE (64 * 72)

__global__ __launch_bounds__(128)
void mma_attn_kernel(const __nv_bfloat16* __restrict__ qh,
                     const __nv_bfloat16* __restrict__ ql,
                     __nv_bfloat16* __restrict__ aoh,
                     __nv_bfloat16* __restrict__ aol) {
    __shared__ __align__(16) __nv_bfloat16 Kh[ASM_ELE];
    __shared__ __align__(16) __nv_bfloat16 Kl[ASM_ELE];
    __shared__ __align__(16) __nv_bfloat16 Vh[ASM_ELE];
    __shared__ __align__(16) __nv_bfloat16 Vl[ASM_ELE];

    int qt = 63 - blockIdx.x;          // heavy tiles first
    int h = blockIdx.y;
    int tid = threadIdx.x;
    int wid = tid >> 5, lane = tid & 31;
    int g = lane >> 2, t = lane & 3;
    int r0 = wid * 16;
    int gA = qt * 64 + r0 + g;

    // ldmatrix lane->address components
    int krow = ((lane >> 4) & 1) * 8 + (lane & 7);   // K non-trans: n row; tiles (nlo,klo),(nlo,khi),(nhi,klo),(nhi,khi)
    int kcol = ((lane >> 3) & 1) * 8;                // K: k half
    int vrow = lane & 15;                            // V trans: key row
    int vcol = (lane >> 4) * 8;                      // V trans: d half

    uint32_t ahq[4][4], alq[4][4];
    {
        size_t rA = (size_t)gA * QKV_N + h * DHEAD;
        size_t rB = (size_t)(gA + 8) * QKV_N + h * DHEAD;
        #pragma unroll
        for (int d16 = 0; d16 < 4; d16++) {
            int cA = d16 * 16 + 2 * t, cB = d16 * 16 + 8 + 2 * t;
            ahq[d16][0] = *(const uint32_t*)&qh[rA + cA];
            ahq[d16][1] = *(const uint32_t*)&qh[rB + cA];
            ahq[d16][2] = *(const uint32_t*)&qh[rA + cB];
            ahq[d16][3] = *(const uint32_t*)&qh[rB + cB];
            alq[d16][0] = *(const uint32_t*)&ql[rA + cA];
            alq[d16][1] = *(const uint32_t*)&ql[rB + cA];
            alq[d16][2] = *(const uint32_t*)&ql[rA + cB];
            alq[d16][3] = *(const uint32_t*)&ql[rB + cB];
        }
    }

    float o[8][4];
    #pragma unroll
    for (int nt = 0; nt < 8; nt++)
        #pragma unroll
        for (int e = 0; e < 4; e++) o[nt][e] = 0.f;
    float m[2] = {-1e30f, -1e30f}, l[2] = {0.f, 0.f};

    for (int kt = 0; kt <= qt; kt++) {
        __syncthreads();
        for (int p = tid; p < 512; p += 128) {
            int rr = p >> 3, c8 = (p & 7) * 8;
            size_t base = (size_t)(kt * 64 + rr) * QKV_N + h * DHEAD + c8;
            *(uint4*)&Kh[rr * 72 + c8] = *(const uint4*)&qh[base + DINNER];
            *(uint4*)&Kl[rr * 72 + c8] = *(const uint4*)&ql[base + DINNER];
            *(uint4*)&Vh[rr * 72 + c8] = *(const uint4*)&qh[base + 2 * DINNER];
            *(uint4*)&Vl[rr * 72 + c8] = *(const uint4*)&ql[base + 2 * DINNER];
        }
        __syncthreads();

        float sc[8][4];
        #pragma unroll
        for (int nt = 0; nt < 8; nt++)
            #pragma unroll
            for (int e = 0; e < 4; e++) sc[nt][e] = 0.f;

        #pragma unroll
        for (int d16 = 0; d16 < 4; d16++) {
            #pragma unroll
            for (int p2 = 0; p2 < 4; p2++) {       // nt pairs
                uint32_t bh0, bh1, bh2, bh3, bl0, bl1, bl2, bl3;
                ldsm4(bh0, bh1, bh2, bh3,
                      &Kh[(p2 * 16 + krow) * 72 + d16 * 16 + kcol]);
                ldsm4(bl0, bl1, bl2, bl3,
                      &Kl[(p2 * 16 + krow) * 72 + d16 * 16 + kcol]);
                mma16816(sc[2*p2],   ahq[d16][0], ahq[d16][1], ahq[d16][2], ahq[d16][3], bh0, bh1);
                mma16816(sc[2*p2],   ahq[d16][0], ahq[d16][1], ahq[d16][2], ahq[d16][3], bl0, bl1);
                mma16816(sc[2*p2],   alq[d16][0], alq[d16][1], alq[d16][2], alq[d16][3], bh0, bh1);
                mma16816(sc[2*p2+1], ahq[d16][0], ahq[d16][1], ahq[d16][2], ahq[d16][3], bh2, bh3);
                mma16816(sc[2*p2+1], ahq[d16][0], ahq[d16][1], ahq[d16][2], ahq[d16][3], bl2, bl3);
                mma16816(sc[2*p2+1], alq[d16][0], alq[d16][1], alq[d16][2], alq[d16][3], bh2, bh3);
            }
        }

        #pragma unroll
        for (int nt = 0; nt < 8; nt++)
            #pragma unroll
            for (int e = 0; e < 4; e++) sc[nt][e] *= 8.f;

        if (kt == qt) {
            #pragma unroll
            for (int nt = 0; nt < 8; nt++) {
                int colb = nt * 8 + 2 * t;
                int rA = r0 + g, rB = r0 + 8 + g;
                if (colb > rA)     sc[nt][0] = -1e30f;
                if (colb + 1 > rA) sc[nt][1] = -1e30f;
                if (colb > rB)     sc[nt][2] = -1e30f;
                if (colb + 1 > rB) sc[nt][3] = -1e30f;
            }
        }

        #pragma unroll
        for (int hf = 0; hf < 2; hf++) {
            float mx = -1e30f;
            #pragma unroll
            for (int nt = 0; nt < 8; nt++) {
                mx = fmaxf(mx, sc[nt][2 * hf]);
                mx = fmaxf(mx, sc[nt][2 * hf + 1]);
            }
            mx = fmaxf(mx, __shfl_xor_sync(0xffffffffu, mx, 1));
            mx = fmaxf(mx, __shfl_xor_sync(0xffffffffu, mx, 2));
            float mnew = fmaxf(m[hf], mx);
            float corr = __expf(m[hf] - mnew);
            m[hf] = mnew;
            float sum = 0.f;
            #pragma unroll
            for (int nt = 0; nt < 8; nt++) {
                float p0 = __expf(sc[nt][2 * hf] - mnew);
                float p1 = __expf(sc[nt][2 * hf + 1] - mnew);
                sc[nt][2 * hf] = p0;
                sc[nt][2 * hf + 1] = p1;
                sum += p0 + p1;
            }
            sum += __shfl_xor_sync(0xffffffffu, sum, 1);
            sum += __shfl_xor_sync(0xffffffffu, sum, 2);
            l[hf] = l[hf] * corr + sum;
            #pragma unroll
            for (int nt = 0; nt < 8; nt++) {
                o[nt][2 * hf] *= corr;
                o[nt][2 * hf + 1] *= corr;
            }
        }

        uint32_t phf[4][4], plf[4][4];
        #pragma unroll
        for (int kk = 0; kk < 4; kk++) {
            split2(sc[2 * kk][0], sc[2 * kk][1], phf[kk][0], plf[kk][0]);
            split2(sc[2 * kk][2], sc[2 * kk][3], phf[kk][1], plf[kk][1]);
            split2(sc[2 * kk + 1][0], sc[2 * kk + 1][1], phf[kk][2], plf[kk][2]);
            split2(sc[2 * kk + 1][2], sc[2 * kk + 1][3], phf[kk][3], plf[kk][3]);
        }

        #pragma unroll
        for (int kk = 0; kk < 4; kk++) {
            #pragma unroll
            for (int p2 = 0; p2 < 4; p2++) {       // nt pairs
                uint32_t vh0, vh1, vh2, vh3, vl0, vl1, vl2, vl3;
                ldsm4t(vh0, vh1, vh2, vh3,
                       &Vh[(kk * 16 + vrow) * 72 + p2 * 16 + vcol]);
                ldsm4t(vl0, vl1, vl2, vl3,
                       &Vl[(kk * 16 + vrow) * 72 + p2 * 16 + vcol]);
                mma16816(o[2*p2],   phf[kk][0], phf[kk][1], phf[kk][2], phf[kk][3], vh0, vh1);
                mma16816(o[2*p2],   phf[kk][0], phf[kk][1], phf[kk][2], phf[kk][3], vl0, vl1);
                mma16816(o[2*p2],   plf[kk][0], plf[kk][1], plf[kk][2], plf[kk][3], vh0, vh1);
                mma16816(o[2*p2+1], phf[kk][0], phf[kk][1], phf[kk][2], phf[kk][3], vh2, vh3);
                mma16816(o[2*p2+1], phf[kk][0], phf[kk][1], phf[kk][2], phf[kk][3], vl2, vl3);
                mma16816(o[2*p2+1], plf[kk][0], plf[kk][1], plf[kk][2], plf[kk][3], vh2, vh3);
            }
        }
    }

    float inv0 = 1.f / l[0], inv1 = 1.f / l[1];
    #pragma unroll
    for (int nt = 0; nt < 8; nt++) {
        int col = h * DHEAD + nt * 8 + 2 * t;
        size_t rA = (size_t)gA * DINNER + col;
        size_t rB = (size_t)(gA + 8) * DINNER + col;
        uint32_t hi, lo;
        split2(o[nt][0] * inv0, o[nt][1] * inv0, hi, lo);
        *(uint32_t*)&aoh[rA] = hi;
        *(uint32_t*)&aol[rA] = lo;
        split2(o[nt][2] * inv1, o[nt][3] * inv1, hi, lo);
        *(uint32_t*)&aoh[rB] = hi;
        *(uint32_t*)&aol[rB] = lo;
    }
}

// ---------------------------------------------------------------------------
extern "C" void kernel_launch(void* const* d_in, const int* in_sizes, int n_in,
                              void* d_out, int out_size) {
    const float* x     = (const float*)d_in[0];
    const float* gamma = (const float*)d_in[1];
    const float* w_qkv = (const float*)d_in[2];
    const float* w_out = (const float*)d_in[3];
    float* out = (float*)d_out;

    __nv_bfloat16 *xh, *xl, *wqh, *wql, *woh, *wol, *qkvh, *qkvl, *aoh, *aol;
    cudaGetSymbolAddress((void**)&xh, g_xh);
    cudaGetSymbolAddress((void**)&xl, g_xl);
    cudaGetSymbolAddress((void**)&wqh, g_wqh);
    cudaGetSymbolAddress((void**)&wql, g_wql);
    cudaGetSymbolAddress((void**)&woh, g_woh);
    cudaGetSymbolAddress((void**)&wol, g_wol);
    cudaGetSymbolAddress((void**)&qkvh, g_qkvh);
    cudaGetSymbolAddress((void**)&qkvl, g_qkvl);
    cudaGetSymbolAddress((void**)&aoh, g_aoh);
    cudaGetSymbolAddress((void**)&aol, g_aol);

    cudaFuncSetAttribute(mma_gemm_kernel<true>,
                         cudaFuncAttributeMaxDynamicSharedMemorySize, GEMM_SMEM);
    cudaFuncSetAttribute(mma_gemm_kernel<false>,
                         cudaFuncAttributeMaxDynamicSharedMemorySize, GEMM_SMEM);

    rms_split_x_kernel<<<N_TOK, 256>>>((const float4*)x, gamma);
    split_w_kernel<<<(DIM * QKV_N / 4) / 256, 256>>>((const float4*)w_qkv, wqh, wql);
    split_w_kernel<<<(DINNER * DIM / 4) / 256, 256>>>((const float4*)w_out, woh, wol);

    mma_gemm_kernel<true><<<dim3(QKV_N / 64, N_TOK / 128), 256, GEMM_SMEM>>>(
        xh, xl, wqh, wql, nullptr, qkvh, qkvl, N_TOK, QKV_N, DIM);

    mma_attn_kernel<<<dim3(64, 8), 128>>>(qkvh, qkvl, aoh, aol);

    mma_gemm_kernel<false><<<dim3(DIM / 64, N_TOK / 128), 256, GEMM_SMEM>>>(
        aoh, aol, woh, wol, out, nullptr, nullptr, N_TOK, DIM, DINNER);
}

// round 12
// speedup vs baseline: 1.4128x; 1.0249x over previous
#include <cuda_runtime.h>
#include <cuda_bf16.h>
#include <math.h>
#include <stdint.h>

#define N_TOK   4096
#define DIM     1024
#define HEADS   8
#define DHEAD   64
#define DINNER  512
#define QKV_N   1536

// Scratch (allocation-free rule: __device__ globals)
__device__ float g_scale[N_TOK];
__device__ __nv_bfloat16 g_xh[(size_t)N_TOK * DIM],     g_xl[(size_t)N_TOK * DIM];
__device__ __nv_bfloat16 g_wqh[(size_t)DIM * QKV_N],    g_wql[(size_t)DIM * QKV_N];
__device__ __nv_bfloat16 g_woh[(size_t)DINNER * DIM],   g_wol[(size_t)DINNER * DIM];
__device__ __nv_bfloat16 g_qkvh[(size_t)N_TOK * QKV_N], g_qkvl[(size_t)N_TOK * QKV_N];
__device__ __nv_bfloat16 g_aoh[(size_t)N_TOK * DINNER], g_aol[(size_t)N_TOK * DINNER];

// ---------------------------------------------------------------------------
// Helpers
// ---------------------------------------------------------------------------
__device__ __forceinline__ void mma16816(float* c,
    uint32_t a0, uint32_t a1, uint32_t a2, uint32_t a3,
    uint32_t b0, uint32_t b1) {
    asm volatile(
        "mma.sync.aligned.m16n8k16.row.col.f32.bf16.bf16.f32 "
        "{%0,%1,%2,%3}, {%4,%5,%6,%7}, {%8,%9}, {%0,%1,%2,%3};"
        : "+f"(c[0]), "+f"(c[1]), "+f"(c[2]), "+f"(c[3])
        : "r"(a0), "r"(a1), "r"(a2), "r"(a3), "r"(b0), "r"(b1));
}
__device__ __forceinline__ void ldsm4(uint32_t& r0, uint32_t& r1,
                                      uint32_t& r2, uint32_t& r3, const void* p) {
    uint32_t a = (uint32_t)__cvta_generic_to_shared(p);
    asm volatile("ldmatrix.sync.aligned.m8n8.x4.shared.b16 {%0,%1,%2,%3}, [%4];"
                 : "=r"(r0), "=r"(r1), "=r"(r2), "=r"(r3) : "r"(a));
}
__device__ __forceinline__ void ldsm4t(uint32_t& r0, uint32_t& r1,
                                       uint32_t& r2, uint32_t& r3, const void* p) {
    uint32_t a = (uint32_t)__cvta_generic_to_shared(p);
    asm volatile("ldmatrix.sync.aligned.m8n8.x4.trans.shared.b16 {%0,%1,%2,%3}, [%4];"
                 : "=r"(r0), "=r"(r1), "=r"(r2), "=r"(r3) : "r"(a));
}
__device__ __forceinline__ void split2(float v0, float v1,
                                       uint32_t& hi, uint32_t& lo) {
    __nv_bfloat16 h0 = __float2bfloat16_rn(v0);
    __nv_bfloat16 h1 = __float2bfloat16_rn(v1);
    __nv_bfloat16 l0 = __float2bfloat16_rn(v0 - __bfloat162float(h0));
    __nv_bfloat16 l1 = __float2bfloat16_rn(v1 - __bfloat162float(h1));
    __nv_bfloat162 hp; hp.x = h0; hp.y = h1;
    __nv_bfloat162 lp; lp.x = l0; lp.y = l1;
    hi = *(uint32_t*)&hp;
    lo = *(uint32_t*)&lp;
}
__device__ __forceinline__ void cp16(uint32_t d, const void* s) {
    asm volatile("cp.async.cg.shared.global [%0], [%1], 16;" :: "r"(d), "l"(s));
}
__device__ __forceinline__ void cpcommit() { asm volatile("cp.async.commit_group;" ::: "memory"); }
__device__ __forceinline__ void cpwait0()  { asm volatile("cp.async.wait_group 0;" ::: "memory"); }
__device__ __forceinline__ void cpwait1()  { asm volatile("cp.async.wait_group 1;" ::: "memory"); }

// ---------------------------------------------------------------------------
// Kernel 1: fused rmsnorm + gamma + bf16 hi/lo split of x.
// ---------------------------------------------------------------------------
__global__ __launch_bounds__(256)
void rms_split_x_kernel(const float4* __restrict__ x,
                        const float* __restrict__ gamma) {
    int row = blockIdx.x;
    float4 v = x[(size_t)row * 256 + threadIdx.x];
    float s = v.x * v.x + v.y * v.y + v.z * v.z + v.w * v.w;
    #pragma unroll
    for (int o = 16; o; o >>= 1) s += __shfl_xor_sync(0xffffffffu, s, o);
    __shared__ float ws[8];
    if ((threadIdx.x & 31) == 0) ws[threadIdx.x >> 5] = s;
    __syncthreads();
    float t = 0.f;
    #pragma unroll
    for (int i = 0; i < 8; i++) t += ws[i];
    float sc = 32.0f / fmaxf(sqrtf(t), 1e-12f);

    int col = threadIdx.x * 4;
    float4 gm = *(const float4*)(gamma + col);
    uint32_t h0, l0, h1, l1;
    split2(v.x * sc * gm.x, v.y * sc * gm.y, h0, l0);
    split2(v.z * sc * gm.z, v.w * sc * gm.w, h1, l1);
    size_t o4 = (size_t)row * DIM + col;
    *(uint2*)&g_xh[o4] = make_uint2(h0, h1);
    *(uint2*)&g_xl[o4] = make_uint2(l0, l1);
}

__global__ void split_w_kernel(const float4* __restrict__ w,
                               __nv_bfloat16* __restrict__ hi,
                               __nv_bfloat16* __restrict__ lo) {
    int i = blockIdx.x * 256 + threadIdx.x;
    float4 v = w[i];
    uint32_t h0, l0, h1, l1;
    split2(v.x, v.y, h0, l0);
    split2(v.z, v.w, h1, l1);
    *(uint2*)&hi[(size_t)4 * i] = make_uint2(h0, h1);
    *(uint2*)&lo[(size_t)4 * i] = make_uint2(l0, l1);
}

// ---------------------------------------------------------------------------
// bf16-split HMMA GEMM: C = (Ah+Al) @ (Bh+Bl), 3-product emulation.
// 128x64 tile, BK=32, 8 warps (4m x 2n), warp tile 32x32, cp.async 2-stage.
// Products interleaved across 4 accumulators (RAW distance 4).
// ---------------------------------------------------------------------------
#define GA_ELE (128 * 40)
#define GB_ELE (32 * 72)
#define GSTAGE_ELE (2 * GA_ELE + 2 * GB_ELE)
#define GEMM_SMEM (2 * GSTAGE_ELE * 2)

template <bool SPLIT_OUT>
__global__ __launch_bounds__(256)
void mma_gemm_kernel(const __nv_bfloat16* __restrict__ Ah,
                     const __nv_bfloat16* __restrict__ Al,
                     const __nv_bfloat16* __restrict__ Bh,
                     const __nv_bfloat16* __restrict__ Bl,
                     float* __restrict__ C,
                     __nv_bfloat16* __restrict__ Ch,
                     __nv_bfloat16* __restrict__ Cl,
                     int M, int N, int K) {
    extern __shared__ __align__(16) __nv_bfloat16 smg[];
    uint32_t smg_u = (uint32_t)__cvta_generic_to_shared(smg);
    int tid = threadIdx.x;
    int wid = tid >> 5, lane = tid & 31;
    int g = lane >> 2, t = lane & 3;
    int wm = wid & 3, wn = wid >> 2;
    int m0 = blockIdx.y * 128, n0 = blockIdx.x * 64;

    int arow = ((lane >> 3) & 1) * 8 + (lane & 7);
    int acol = (lane >> 4) * 8;
    int brow = lane & 15;
    int bcol = (lane >> 4) * 8;

    int a0r = tid >> 2,         a0k = (tid & 3) * 8;
    int a1r = (tid + 256) >> 2, a1k = ((tid + 256) & 3) * 8;
    int lbr = tid >> 3,         lbn = (tid & 7) * 8;

    #define G_LOAD(buf_, k0_) do {                                              \
        uint32_t sb = smg_u + (buf_) * (GSTAGE_ELE * 2);                        \
        cp16(sb + (a0r * 40 + a0k) * 2,                                         \
             Ah + (size_t)(m0 + a0r) * K + (k0_) + a0k);                        \
        cp16(sb + (a1r * 40 + a1k) * 2,                                         \
             Ah + (size_t)(m0 + a1r) * K + (k0_) + a1k);                        \
        cp16(sb + (GA_ELE + a0r * 40 + a0k) * 2,                                \
             Al + (size_t)(m0 + a0r) * K + (k0_) + a0k);                        \
        cp16(sb + (GA_ELE + a1r * 40 + a1k) * 2,                                \
             Al + (size_t)(m0 + a1r) * K + (k0_) + a1k);                        \
        cp16(sb + (2 * GA_ELE + lbr * 72 + lbn) * 2,                            \
             Bh + (size_t)((k0_) + lbr) * N + n0 + lbn);                        \
        cp16(sb + (2 * GA_ELE + GB_ELE + lbr * 72 + lbn) * 2,                   \
             Bl + (size_t)((k0_) + lbr) * N + n0 + lbn);                        \
        cpcommit();                                                             \
    } while (0)

    float c[2][4][4];
    #pragma unroll
    for (int mt = 0; mt < 2; mt++)
        #pragma unroll
        for (int nt = 0; nt < 4; nt++)
            #pragma unroll
            for (int e = 0; e < 4; e++) c[mt][nt][e] = 0.f;

    const int S = K / 32;
    G_LOAD(0, 0);
    for (int s = 0; s < S; s++) {
        if (s + 1 < S) { G_LOAD((s + 1) & 1, (s + 1) * 32); cpwait1(); }
        else           { cpwait0(); }
        __syncthreads();

        const __nv_bfloat16* stg = smg + (s & 1) * GSTAGE_ELE;
        const __nv_bfloat16* As0 = stg;
        const __nv_bfloat16* As1 = stg + GA_ELE;
        const __nv_bfloat16* Bs0 = stg + 2 * GA_ELE;
        const __nv_bfloat16* Bs1 = stg + 2 * GA_ELE + GB_ELE;

        #pragma unroll
        for (int kk = 0; kk < 32; kk += 16) {
            uint32_t ah[2][4], al[2][4];
            #pragma unroll
            for (int mt = 0; mt < 2; mt++) {
                int r = wm * 32 + mt * 16;
                ldsm4(ah[mt][0], ah[mt][1], ah[mt][2], ah[mt][3],
                      &As0[(r + arow) * 40 + kk + acol]);
                ldsm4(al[mt][0], al[mt][1], al[mt][2], al[mt][3],
                      &As1[(r + arow) * 40 + kk + acol]);
            }
            #pragma unroll
            for (int p2 = 0; p2 < 2; p2++) {
                uint32_t bh0, bh1, bh2, bh3, bl0, bl1, bl2, bl3;
                ldsm4t(bh0, bh1, bh2, bh3,
                       &Bs0[(kk + brow) * 72 + wn * 32 + p2 * 16 + bcol]);
                ldsm4t(bl0, bl1, bl2, bl3,
                       &Bs1[(kk + brow) * 72 + wn * 32 + p2 * 16 + bcol]);
                // products interleaved: same-acc RAW distance = 4
                mma16816(c[0][2*p2],   ah[0][0], ah[0][1], ah[0][2], ah[0][3], bh0, bh1);
                mma16816(c[0][2*p2+1], ah[0][0], ah[0][1], ah[0][2], ah[0][3], bh2, bh3);
                mma16816(c[1][2*p2],   ah[1][0], ah[1][1], ah[1][2], ah[1][3], bh0, bh1);
                mma16816(c[1][2*p2+1], ah[1][0], ah[1][1], ah[1][2], ah[1][3], bh2, bh3);
                mma16816(c[0][2*p2],   ah[0][0], ah[0][1], ah[0][2], ah[0][3], bl0, bl1);
                mma16816(c[0][2*p2+1], ah[0][0], ah[0][1], ah[0][2], ah[0][3], bl2, bl3);
                mma16816(c[1][2*p2],   ah[1][0], ah[1][1], ah[1][2], ah[1][3], bl0, bl1);
                mma16816(c[1][2*p2+1], ah[1][0], ah[1][1], ah[1][2], ah[1][3], bl2, bl3);
                mma16816(c[0][2*p2],   al[0][0], al[0][1], al[0][2], al[0][3], bh0, bh1);
                mma16816(c[0][2*p2+1], al[0][0], al[0][1], al[0][2], al[0][3], bh2, bh3);
                mma16816(c[1][2*p2],   al[1][0], al[1][1], al[1][2], al[1][3], bh0, bh1);
                mma16816(c[1][2*p2+1], al[1][0], al[1][1], al[1][2], al[1][3], bh2, bh3);
            }
        }
        __syncthreads();
    }

    #pragma unroll
    for (int mt = 0; mt < 2; mt++) {
        #pragma unroll
        for (int nt = 0; nt < 4; nt++) {
            int rowA = m0 + wm * 32 + mt * 16 + g;
            int col = n0 + wn * 32 + nt * 8 + 2 * t;
            if (SPLIT_OUT) {
                uint32_t hi, lo;
                split2(c[mt][nt][0], c[mt][nt][1], hi, lo);
                *(uint32_t*)&Ch[(size_t)rowA * N + col] = hi;
                *(uint32_t*)&Cl[(size_t)rowA * N + col] = lo;
                split2(c[mt][nt][2], c[mt][nt][3], hi, lo);
                *(uint32_t*)&Ch[(size_t)(rowA + 8) * N + col] = hi;
                *(uint32_t*)&Cl[(size_t)(rowA + 8) * N + col] = lo;
            } else {
                *(float2*)&C[(size_t)rowA * N + col] =
                    make_float2(c[mt][nt][0], c[mt][nt][1]);
                *(float2*)&C[(size_t)(rowA + 8) * N + col] =
                    make_float2(c[mt][nt][2], c[mt][nt][3]);
            }
        }
    }
    #undef G_LOAD
}

// ---------------------------------------------------------------------------
// Flash attention: HMMA bf16-split, 64-row Q tiles, 128 thr = 4 warps,
// Q frags in registers. K/V tiles cp.async DOUBLE-BUFFERED (73.7 KB dyn smem):
// stage kt+1 loads overlap all of stage kt's S-mma + softmax + PV.
// ---------------------------------------------------------------------------
#define AT_ARR 4608                      // 64 x 72 elems
#define AT_STAGE (4 * AT_ARR)            // Kh | Kl | Vh | Vl
#define ATT_SMEM (2 * AT_STAGE * 2)      // 73728 bytes

__global__ __launch_bounds__(128)
void mma_attn_kernel(const __nv_bfloat16* __restrict__ qh,
                     const __nv_bfloat16* __restrict__ ql,
                     __nv_bfloat16* __restrict__ aoh,
                     __nv_bfloat16* __restrict__ aol) {
    extern __shared__ __align__(16) __nv_bfloat16 smb[];
    uint32_t smb_u = (uint32_t)__cvta_generic_to_shared(smb);

    int qt = 63 - blockIdx.x;          // heavy tiles first
    int h = blockIdx.y;
    int tid = threadIdx.x;
    int wid = tid >> 5, lane = tid & 31;
    int g = lane >> 2, t = lane & 3;
    int r0 = wid * 16;
    int gA = qt * 64 + r0 + g;

    int krow = ((lane >> 4) & 1) * 8 + (lane & 7);
    int kcol = ((lane >> 3) & 1) * 8;
    int vrow = lane & 15;
    int vcol = (lane >> 4) * 8;

    // stage loader: 16 cp16 per thread
    #define LOAD_KV(kt_, buf_) do {                                            \
        uint32_t sbase = smb_u + (buf_) * (AT_STAGE * 2);                      \
        _Pragma("unroll")                                                      \
        for (int j = 0; j < 4; j++) {                                          \
            int p = tid + j * 128;                                             \
            int rr = p >> 3, c8 = (p & 7) * 8;                                 \
            uint32_t dso = rr * 144 + c8 * 2;                                  \
            size_t base = (size_t)((kt_) * 64 + rr) * QKV_N + h * DHEAD + c8;  \
            cp16(sbase + dso,                  qh + base + DINNER);            \
            cp16(sbase + AT_ARR * 2 + dso,     ql + base + DINNER);            \
            cp16(sbase + 2 * AT_ARR * 2 + dso, qh + base + 2 * DINNER);        \
            cp16(sbase + 3 * AT_ARR * 2 + dso, ql + base + 2 * DINNER);        \
        }                                                                      \
        cpcommit();                                                            \
    } while (0)

    uint32_t ahq[4][4], alq[4][4];
    {
        size_t rA = (size_t)gA * QKV_N + h * DHEAD;
        size_t rB = (size_t)(gA + 8) * QKV_N + h * DHEAD;
        #pragma unroll
        for (int d16 = 0; d16 < 4; d16++) {
            int cA = d16 * 16 + 2 * t, cB = d16 * 16 + 8 + 2 * t;
            ahq[d16][0] = *(const uint32_t*)&qh[rA + cA];
            ahq[d16][1] = *(const uint32_t*)&qh[rB + cA];
            ahq[d16][2] = *(const uint32_t*)&qh[rA + cB];
            ahq[d16][3] = *(const uint32_t*)&qh[rB + cB];
            alq[d16][0] = *(const uint32_t*)&ql[rA + cA];
            alq[d16][1] = *(const uint32_t*)&ql[rB + cA];
            alq[d16][2] = *(const uint32_t*)&ql[rA + cB];
            alq[d16][3] = *(const uint32_t*)&ql[rB + cB];
        }
    }

    float o[8][4];
    #pragma unroll
    for (int nt = 0; nt < 8; nt++)
        #pragma unroll
        for (int e = 0; e < 4; e++) o[nt][e] = 0.f;
    float m[2] = {-1e30f, -1e30f}, l[2] = {0.f, 0.f};

    LOAD_KV(0, 0);

    for (int kt = 0; kt <= qt; kt++) {
        __syncthreads();                                    // prev compute done
        if (kt < qt) { LOAD_KV(kt + 1, (kt + 1) & 1); cpwait1(); }
        else         { cpwait0(); }
        __syncthreads();                                    // stage kt visible

        const __nv_bfloat16* stg = smb + (kt & 1) * AT_STAGE;
        const __nv_bfloat16* Kh = stg;
        const __nv_bfloat16* Kl = stg + AT_ARR;
        const __nv_bfloat16* Vh = stg + 2 * AT_ARR;
        const __nv_bfloat16* Vl = stg + 3 * AT_ARR;

        float sc[8][4];
        #pragma unroll
        for (int nt = 0; nt < 8; nt++)
            #pragma unroll
            for (int e = 0; e < 4; e++) sc[nt][e] = 0.f;

        #pragma unroll
        for (int d16 = 0; d16 < 4; d16++) {
            #pragma unroll
            for (int p2 = 0; p2 < 4; p2++) {
                uint32_t bh0, bh1, bh2, bh3, bl0, bl1, bl2, bl3;
                ldsm4(bh0, bh1, bh2, bh3,
                      &Kh[(p2 * 16 + krow) * 72 + d16 * 16 + kcol]);
                ldsm4(bl0, bl1, bl2, bl3,
                      &Kl[(p2 * 16 + krow) * 72 + d16 * 16 + kcol]);
                mma16816(sc[2*p2],   ahq[d16][0], ahq[d16][1], ahq[d16][2], ahq[d16][3], bh0, bh1);
                mma16816(sc[2*p2+1], ahq[d16][0], ahq[d16][1], ahq[d16][2], ahq[d16][3], bh2, bh3);
                mma16816(sc[2*p2],   ahq[d16][0], ahq[d16][1], ahq[d16][2], ahq[d16][3], bl0, bl1);
                mma16816(sc[2*p2+1], ahq[d16][0], ahq[d16][1], ahq[d16][2], ahq[d16][3], bl2, bl3);
                mma16816(sc[2*p2],   alq[d16][0], alq[d16][1], alq[d16][2], alq[d16][3], bh0, bh1);
                mma16816(sc[2*p2+1], alq[d16][0], alq[d16][1], alq[d16][2], alq[d16][3], bh2, bh3);
            }
        }

        #pragma unroll
        for (int nt = 0; nt < 8; nt++)
            #pragma unroll
            for (int e = 0; e < 4; e++) sc[nt][e] *= 8.f;

        if (kt == qt) {
            #pragma unroll
            for (int nt = 0; nt < 8; nt++) {
                int colb = nt * 8 + 2 * t;
                int rA = r0 + g, rB = r0 + 8 + g;
                if (colb > rA)     sc[nt][0] = -1e30f;
                if (colb + 1 > rA) sc[nt][1] = -1e30f;
                if (colb > rB)     sc[nt][2] = -1e30f;
                if (colb + 1 > rB) sc[nt][3] = -1e30f;
            }
        }

        #pragma unroll
        for (int hf = 0; hf < 2; hf++) {
            float mx = -1e30f;
            #pragma unroll
            for (int nt = 0; nt < 8; nt++) {
                mx = fmaxf(mx, sc[nt][2 * hf]);
                mx = fmaxf(mx, sc[nt][2 * hf + 1]);
            }
            mx = fmaxf(mx, __shfl_xor_sync(0xffffffffu, mx, 1));
            mx = fmaxf(mx, __shfl_xor_sync(0xffffffffu, mx, 2));
            float mnew = fmaxf(m[hf], mx);
            float corr = __expf(m[hf] - mnew);
            m[hf] = mnew;
            float sum = 0.f;
            #pragma unroll
            for (int nt = 0; nt < 8; nt++) {
                float p0 = __expf(sc[nt][2 * hf] - mnew);
                float p1 = __expf(sc[nt][2 * hf + 1] - mnew);
                sc[nt][2 * hf] = p0;
                sc[nt][2 * hf + 1] = p1;
                sum += p0 + p1;
            }
            sum += __shfl_xor_sync(0xffffffffu, sum, 1);
            sum += __shfl_xor_sync(0xffffffffu, sum, 2);
            l[hf] = l[hf] * corr + sum;
            #pragma unroll
            for (int nt = 0; nt < 8; nt++) {
                o[nt][2 * hf] *= corr;
                o[nt][2 * hf + 1] *= corr;
            }
        }

        uint32_t phf[4][4], plf[4][4];
        #pragma unroll
        for (int kk = 0; kk < 4; kk++) {
            split2(sc[2 * kk][0], sc[2 * kk][1], phf[kk][0], plf[kk][0]);
            split2(sc[2 * kk][2], sc[2 * kk][3], phf[kk][1], plf[kk][1]);
            split2(sc[2 * kk + 1][0], sc[2 * kk + 1][1], phf[kk][2], plf[kk][2]);
            split2(sc[2 * kk + 1][2], sc[2 * kk + 1][3], phf[kk][3], plf[kk][3]);
        }

        #pragma unroll
        for (int kk = 0; kk < 4; kk++) {
            #pragma unroll
            for (int p2 = 0; p2 < 4; p2++) {
                uint32_t vh0, vh1, vh2, vh3, vl0, vl1, vl2, vl3;
                ldsm4t(vh0, vh1, vh2, vh3,
                       &Vh[(kk * 16 + vrow) * 72 + p2 * 16 + vcol]);
                ldsm4t(vl0, vl1, vl2, vl3,
                       &Vl[(kk * 16 + vrow) * 72 + p2 * 16 + vcol]);
                mma16816(o[2*p2],   phf[kk][0], phf[kk][1], phf[kk][2], phf[kk][3], vh0, vh1);
                mma16816(o[2*p2+1], phf[kk][0], phf[kk][1], phf[kk][2], phf[kk][3], vh2, vh3);
                mma16816(o[2*p2],   phf[kk][0], phf[kk][1], phf[kk][2], phf[kk][3], vl0, vl1);
                mma16816(o[2*p2+1], phf[kk][0], phf[kk][1], phf[kk][2], phf[kk][3], vl2, vl3);
                mma16816(o[2*p2],   plf[kk][0], plf[kk][1], plf[kk][2], plf[kk][3], vh0, vh1);
                mma16816(o[2*p2+1], plf[kk][0], plf[kk][1], plf[kk][2], plf[kk][3], vh2, vh3);
            }
        }
    }

    float inv0 = 1.f / l[0], inv1 = 1.f / l[1];
    #pragma unroll
    for (int nt = 0; nt < 8; nt++) {
        int col = h * DHEAD + nt * 8 + 2 * t;
        size_t rA = (size_t)gA * DINNER + col;
        size_t rB = (size_t)(gA + 8) * DINNER + col;
        uint32_t hi, lo;
        split2(o[nt][0] * inv0, o[nt][1] * inv0, hi, lo);
        *(uint32_t*)&aoh[rA] = hi;
        *(uint32_t*)&aol[rA] = lo;
        split2(o[nt][2] * inv1, o[nt][3] * inv1, hi, lo);
        *(uint32_t*)&aoh[rB] = hi;
        *(uint32_t*)&aol[rB] = lo;
    }
    #undef LOAD_KV
}

// ---------------------------------------------------------------------------
extern "C" void kernel_launch(void* const* d_in, const int* in_sizes, int n_in,
                              void* d_out, int out_size) {
    const float* x     = (const float*)d_in[0];
    const float* gamma = (const float*)d_in[1];
    const float* w_qkv = (const float*)d_in[2];
    const float* w_out = (const float*)d_in[3];
    float* out = (float*)d_out;

    __nv_bfloat16 *xh, *xl, *wqh, *wql, *woh, *wol, *qkvh, *qkvl, *aoh, *aol;
    cudaGetSymbolAddress((void**)&xh, g_xh);
    cudaGetSymbolAddress((void**)&xl, g_xl);
    cudaGetSymbolAddress((void**)&wqh, g_wqh);
    cudaGetSymbolAddress((void**)&wql, g_wql);
    cudaGetSymbolAddress((void**)&woh, g_woh);
    cudaGetSymbolAddress((void**)&wol, g_wol);
    cudaGetSymbolAddress((void**)&qkvh, g_qkvh);
    cudaGetSymbolAddress((void**)&qkvl, g_qkvl);
    cudaGetSymbolAddress((void**)&aoh, g_aoh);
    cudaGetSymbolAddress((void**)&aol, g_aol);

    cudaFuncSetAttribute(mma_gemm_kernel<true>,
                         cudaFuncAttributeMaxDynamicSharedMemorySize, GEMM_SMEM);
    cudaFuncSetAttribute(mma_gemm_kernel<false>,
                         cudaFuncAttributeMaxDynamicSharedMemorySize, GEMM_SMEM);
    cudaFuncSetAttribute(mma_attn_kernel,
                         cudaFuncAttributeMaxDynamicSharedMemorySize, ATT_SMEM);

    rms_split_x_kernel<<<N_TOK, 256>>>((const float4*)x, gamma);
    split_w_kernel<<<(DIM * QKV_N / 4) / 256, 256>>>((const float4*)w_qkv, wqh, wql);
    split_w_kernel<<<(DINNER * DIM / 4) / 256, 256>>>((const float4*)w_out, woh, wol);

    mma_gemm_kernel<true><<<dim3(QKV_N / 64, N_TOK / 128), 256, GEMM_SMEM>>>(
        xh, xl, wqh, wql, nullptr, qkvh, qkvl, N_TOK, QKV_N, DIM);

    mma_attn_kernel<<<dim3(64, 8), 128, ATT_SMEM>>>(qkvh, qkvl, aoh, aol);

    mma_gemm_kernel<false><<<dim3(DIM / 64, N_TOK / 128), 256, GEMM_SMEM>>>(
        aoh, aol, woh, wol, out, nullptr, nullptr, N_TOK, DIM, DINNER);
}